// round 1
// baseline (speedup 1.0000x reference)
#include <cuda_runtime.h>
#include <math.h>

#define BB   2
#define C    128
#define NPT  2048
#define H    4
#define D    32
#define KNN  20
#define C2   256

// ---------------- scratch (device globals; no runtime alloc) ----------------
__device__ float    g_xx[BB*NPT];
__device__ float    g_q[BB*H*NPT*D];
__device__ float    g_k[BB*H*NPT*D];
__device__ float    g_v[BB*H*NPT*D];
__device__ float    g_gram[(size_t)BB*NPT*NPT];       // 33.5 MB
__device__ int      g_idx[BB*NPT*KNN];
__device__ unsigned g_bits[BB*NPT*(NPT/32)];          // knn bitsets
__device__ int      g_cnt[BB*NPT];
__device__ int      g_adj[BB*NPT*KNN];
__device__ float    g_av[(size_t)BB*NPT*C];           // (B,N,C)
__device__ float    g_Wh[C2*C2];                      // combined [w1x | w1a@wm]
__device__ float    g_bh[C2];
__device__ float    g_h[(size_t)BB*NPT*C2];           // pre-BN h, (B*N, 2C)
__device__ float    g_sum[C2], g_sumsq[C2];
__device__ float    g_scale[C2], g_shift[C2];

// ---------------- K0: per-point squared norm ----------------
__global__ void k_xx(const float* __restrict__ x){
    int i = blockIdx.x*blockDim.x + threadIdx.x;
    if (i >= BB*NPT) return;
    int b = i / NPT, n = i % NPT;
    const float* xp = x + (size_t)b*C*NPT + n;
    float s = 0.f;
    #pragma unroll
    for (int c = 0; c < C; c++){ float v = xp[(size_t)c*NPT]; s += v*v; }
    g_xx[i] = s;
}

// ---------------- K1: fused QKV GEMM -> (B,H,N,D) layouts ----------------
__global__ __launch_bounds__(256) void k_qkv(
    const float* __restrict__ x,
    const float* __restrict__ wq, const float* __restrict__ bq,
    const float* __restrict__ wk, const float* __restrict__ bk,
    const float* __restrict__ wv, const float* __restrict__ bv)
{
    __shared__ float As[32][65];
    __shared__ float Ws[32][65];
    int b   = blockIdx.z;
    int n0  = blockIdx.x*64;
    int oc0 = blockIdx.y*64;
    int tid = threadIdx.x;
    int tx = tid & 15, ty = tid >> 4;
    float acc[4][4] = {};
    for (int k0 = 0; k0 < C; k0 += 32){
        #pragma unroll
        for (int it = 0; it < 8; it++){
            int i = tid & 63, kk = (tid >> 6) + it*4;
            As[kk][i] = x[(size_t)b*C*NPT + (size_t)(k0+kk)*NPT + n0 + i];
        }
        #pragma unroll
        for (int it = 0; it < 8; it++){
            int kk = tid & 31, j = (tid >> 5) + it*8;
            int oc = oc0 + j;
            const float* wp = (oc < C) ? wq : (oc < 2*C ? wk : wv);
            int ocl = oc & (C-1);
            Ws[kk][j] = wp[ocl*C + k0 + kk];
        }
        __syncthreads();
        #pragma unroll
        for (int kk = 0; kk < 32; kk++){
            float a[4], w[4];
            #pragma unroll
            for (int u = 0; u < 4; u++){ a[u] = As[kk][ty*4+u]; w[u] = Ws[kk][tx*4+u]; }
            #pragma unroll
            for (int i = 0; i < 4; i++)
                #pragma unroll
                for (int j = 0; j < 4; j++)
                    acc[i][j] = fmaf(a[i], w[j], acc[i][j]);
        }
        __syncthreads();
    }
    #pragma unroll
    for (int i = 0; i < 4; i++){
        int n = n0 + ty*4 + i;
        #pragma unroll
        for (int j = 0; j < 4; j++){
            int oc = oc0 + tx*4 + j;
            int t = oc >> 7, ocl = oc & (C-1);
            int h = ocl >> 5, d = ocl & 31;
            float bias = (t==0 ? bq : (t==1 ? bk : bv))[ocl];
            float* dst = (t==0 ? g_q : (t==1 ? g_k : g_v));
            dst[(((size_t)b*H + h)*NPT + n)*D + d] = acc[i][j] + bias;
        }
    }
}

// ---------------- K2a: gram GEMM  G[n,m] = 2*x_n.x_m - |x_m|^2 ----------------
__global__ __launch_bounds__(256) void k_gram(const float* __restrict__ x){
    __shared__ float As[32][132];
    __shared__ float Bs[32][132];
    int b  = blockIdx.z;
    int n0 = blockIdx.y*128;
    int m0 = blockIdx.x*128;
    int tid = threadIdx.x;
    int tx = tid & 15, ty = tid >> 4;
    const float* xb = x + (size_t)b*C*NPT;
    float acc[8][8] = {};
    for (int k0 = 0; k0 < C; k0 += 32){
        #pragma unroll
        for (int it = 0; it < 16; it++){
            int i = tid & 127, kk = (tid >> 7) + it*2;
            As[kk][i] = xb[(size_t)(k0+kk)*NPT + n0 + i];
            Bs[kk][i] = xb[(size_t)(k0+kk)*NPT + m0 + i];
        }
        __syncthreads();
        #pragma unroll
        for (int kk = 0; kk < 32; kk++){
            float4 a0 = *(const float4*)&As[kk][ty*8];
            float4 a1 = *(const float4*)&As[kk][ty*8+4];
            float4 b0 = *(const float4*)&Bs[kk][tx*8];
            float4 b1 = *(const float4*)&Bs[kk][tx*8+4];
            float a[8] = {a0.x,a0.y,a0.z,a0.w,a1.x,a1.y,a1.z,a1.w};
            float bb[8] = {b0.x,b0.y,b0.z,b0.w,b1.x,b1.y,b1.z,b1.w};
            #pragma unroll
            for (int i = 0; i < 8; i++)
                #pragma unroll
                for (int j = 0; j < 8; j++)
                    acc[i][j] = fmaf(a[i], bb[j], acc[i][j]);
        }
        __syncthreads();
    }
    float* gp = g_gram + (size_t)b*NPT*NPT;
    #pragma unroll
    for (int i = 0; i < 8; i++){
        int n = n0 + ty*8 + i;
        #pragma unroll
        for (int j = 0; j < 8; j++){
            int m = m0 + tx*8 + j;
            gp[(size_t)n*NPT + m] = 2.f*acc[i][j] - g_xx[b*NPT + m];
        }
    }
}

// ---------------- K2b: top-K=20 per row (iterative register argmax) ----------------
__global__ __launch_bounds__(256) void k_topk(){
    int row = blockIdx.x;                 // b*NPT + n
    const float* g = g_gram + (size_t)row*NPT;
    int tid = threadIdx.x;
    float v[8];
    #pragma unroll
    for (int j = 0; j < 8; j++) v[j] = g[tid + j*256];
    __shared__ float sv[8]; __shared__ int si[8];
    __shared__ int swin;
    int lane = tid & 31, wid = tid >> 5;
    for (int r = 0; r < KNN; r++){
        float bv = v[0]; int bj = 0;
        #pragma unroll
        for (int j = 1; j < 8; j++) if (v[j] > bv){ bv = v[j]; bj = j; }
        int bi = tid + bj*256;
        #pragma unroll
        for (int off = 16; off; off >>= 1){
            float ov = __shfl_down_sync(0xffffffffu, bv, off);
            int   oi = __shfl_down_sync(0xffffffffu, bi, off);
            if (ov > bv || (ov == bv && oi < bi)){ bv = ov; bi = oi; }
        }
        if (lane == 0){ sv[wid] = bv; si[wid] = bi; }
        __syncthreads();
        if (wid == 0){
            float bv2 = (lane < 8) ? sv[lane] : -3.4e38f;
            int   bi2 = (lane < 8) ? si[lane] : 0x7fffffff;
            #pragma unroll
            for (int off = 4; off; off >>= 1){
                float ov = __shfl_down_sync(0xffffffffu, bv2, off);
                int   oi = __shfl_down_sync(0xffffffffu, bi2, off);
                if (ov > bv2 || (ov == bv2 && oi < bi2)){ bv2 = ov; bi2 = oi; }
            }
            if (lane == 0){
                swin = bi2;
                g_idx[row*KNN + r] = bi2;
                atomicOr(&g_bits[(size_t)row*(NPT/32) + (bi2 >> 5)], 1u << (bi2 & 31));
            }
        }
        __syncthreads();
        int w = swin;
        if ((w & 255) == tid) v[w >> 8] = -3.4e38f;
    }
}

// ---------------- K3: mutual-KNN compaction ----------------
__global__ void k_mutual(){
    int row = blockIdx.x*8 + (threadIdx.x >> 5);
    int lane = threadIdx.x & 31;
    if (row >= BB*NPT) return;
    int b = row / NPT, n = row % NPT;
    int m = 0; bool ok = false;
    if (lane < KNN){
        m = g_idx[row*KNN + lane];
        ok = (g_bits[(size_t)(b*NPT + m)*(NPT/32) + (n >> 5)] >> (n & 31)) & 1u;
    }
    unsigned ball = __ballot_sync(0xffffffffu, ok);
    int pos = __popc(ball & ((1u << lane) - 1u));
    if (ok) g_adj[row*KNN + pos] = m;
    if (lane == 0) g_cnt[row] = __popc(ball);
}

// ---------------- K4: sparse attention (warp = head) ----------------
__global__ __launch_bounds__(128) void k_attn(){
    int row = blockIdx.x;              // b*NPT + n
    int b = row >> 11, n = row & (NPT-1);
    int tid = threadIdx.x;
    int h = tid >> 5, lane = tid & 31;
    __shared__ int adj[KNN]; __shared__ int scnt;
    if (tid < KNN) adj[tid] = g_adj[row*KNN + tid];
    if (tid == 0)  scnt = g_cnt[row];
    __syncthreads();
    int cnt = scnt;
    size_t hb = ((size_t)(b*H + h))*NPT*D;
    float ql = g_q[hb + (size_t)n*D + lane];
    float sc = -3.4e38f;
    for (int j = 0; j < cnt; j++){
        float pv = ql * g_k[hb + (size_t)adj[j]*D + lane];
        #pragma unroll
        for (int off = 16; off; off >>= 1) pv += __shfl_xor_sync(0xffffffffu, pv, off);
        if (lane == j) sc = pv * 0.17677669529663687f;   // 1/sqrt(32)
    }
    float mx = sc;
    #pragma unroll
    for (int off = 16; off; off >>= 1) mx = fmaxf(mx, __shfl_xor_sync(0xffffffffu, mx, off));
    float e = (lane < cnt) ? expf(sc - mx) : 0.f;
    float se = e;
    #pragma unroll
    for (int off = 16; off; off >>= 1) se += __shfl_xor_sync(0xffffffffu, se, off);
    float p = e / se;
    float acc = 0.f;
    for (int j = 0; j < cnt; j++){
        float pj = __shfl_sync(0xffffffffu, p, j);
        acc = fmaf(pj, g_v[hb + (size_t)adj[j]*D + lane], acc);
    }
    g_av[(size_t)row*C + h*D + lane] = acc;
}

// ---------------- K5a: fold wm into w1  (Wh = [w1x | w1a@wm], bh = b1 + w1a@bm) ----------------
__global__ __launch_bounds__(128) void k_combine(
    const float* __restrict__ w1, const float* __restrict__ b1,
    const float* __restrict__ wm, const float* __restrict__ bm)
{
    int oc = blockIdx.x; int c = threadIdx.x;    // 256 blocks x 128 threads
    float s = 0.f;
    for (int c2 = 0; c2 < C; c2++)
        s = fmaf(w1[oc*C2 + C + c2], wm[c2*C + c], s);
    g_Wh[oc*C2 + C + c] = s;
    g_Wh[oc*C2 + c] = w1[oc*C2 + c];
    __shared__ float red[128];
    red[c] = w1[oc*C2 + C + c] * bm[c];
    __syncthreads();
    for (int s2 = 64; s2; s2 >>= 1){ if (c < s2) red[c] += red[c + s2]; __syncthreads(); }
    if (c == 0) g_bh[oc] = b1[oc] + red[0];
}

// ---------------- K5b: h = Wh @ [x; av] + bh  -> g_h (B*N, 2C) ----------------
__global__ __launch_bounds__(256) void k_hgemm(const float* __restrict__ x){
    __shared__ float As[32][65], Ws[32][65];
    int r0 = blockIdx.x*64, oc0 = blockIdx.y*64;
    int b = r0 / NPT, n0 = r0 % NPT;
    int tid = threadIdx.x, tx = tid & 15, ty = tid >> 4;
    float acc[4][4] = {};
    for (int k0 = 0; k0 < C2; k0 += 32){
        if (k0 < C){
            #pragma unroll
            for (int it = 0; it < 8; it++){
                int i = tid & 63, kk = (tid >> 6) + it*4;
                As[kk][i] = x[(size_t)b*C*NPT + (size_t)(k0+kk)*NPT + n0 + i];
            }
        } else {
            #pragma unroll
            for (int it = 0; it < 8; it++){
                int kk = tid & 31, i = (tid >> 5) + it*8;
                As[kk][i] = g_av[(size_t)(r0+i)*C + (k0 - C + kk)];
            }
        }
        #pragma unroll
        for (int it = 0; it < 8; it++){
            int kk = tid & 31, j = (tid >> 5) + it*8;
            Ws[kk][j] = g_Wh[(oc0+j)*C2 + k0 + kk];
        }
        __syncthreads();
        #pragma unroll
        for (int kk = 0; kk < 32; kk++){
            float a[4], w[4];
            #pragma unroll
            for (int u = 0; u < 4; u++){ a[u] = As[kk][ty*4+u]; w[u] = Ws[kk][tx*4+u]; }
            #pragma unroll
            for (int i = 0; i < 4; i++)
                #pragma unroll
                for (int j = 0; j < 4; j++)
                    acc[i][j] = fmaf(a[i], w[j], acc[i][j]);
        }
        __syncthreads();
    }
    #pragma unroll
    for (int i = 0; i < 4; i++){
        int r = r0 + ty*4 + i;
        #pragma unroll
        for (int j = 0; j < 4; j++){
            int oc = oc0 + tx*4 + j;
            g_h[(size_t)r*C2 + oc] = acc[i][j] + g_bh[oc];
        }
    }
}

// ---------------- K5c: BN batch stats ----------------
__global__ __launch_bounds__(256) void k_stats(){
    int oc = threadIdx.x;
    int r0 = blockIdx.x*64;
    float s = 0.f, s2 = 0.f;
    for (int i = 0; i < 64; i++){
        float v = g_h[(size_t)(r0+i)*C2 + oc];
        s += v; s2 = fmaf(v, v, s2);
    }
    atomicAdd(&g_sum[oc], s);
    atomicAdd(&g_sumsq[oc], s2);
}

__global__ __launch_bounds__(256) void k_finstats(const float* __restrict__ gamma,
                                                  const float* __restrict__ beta){
    int oc = threadIdx.x;
    float inv = 1.f / (float)(BB*NPT);
    float mean = g_sum[oc] * inv;
    float var  = g_sumsq[oc] * inv - mean*mean;
    float rstd = 1.f / sqrtf(var + 1e-5f);
    g_scale[oc] = rstd * gamma[oc];
    g_shift[oc] = beta[oc] - mean * rstd * gamma[oc];
}

// ---------------- K5d: out = x + w2 @ relu(bn(h)) + b2 ----------------
__global__ __launch_bounds__(256) void k_out(const float* __restrict__ x,
                                             const float* __restrict__ w2,
                                             const float* __restrict__ b2,
                                             float* __restrict__ out){
    __shared__ float As[32][65], Ws[32][65];
    int r0 = blockIdx.x*64, c0 = blockIdx.y*64;
    int b = r0 / NPT, n0 = r0 % NPT;
    int tid = threadIdx.x, tx = tid & 15, ty = tid >> 4;
    float acc[4][4] = {};
    for (int k0 = 0; k0 < C2; k0 += 32){
        #pragma unroll
        for (int it = 0; it < 8; it++){
            int kk = tid & 31, i = (tid >> 5) + it*8;
            float v = g_h[(size_t)(r0+i)*C2 + k0 + kk];
            As[kk][i] = fmaxf(fmaf(v, g_scale[k0+kk], g_shift[k0+kk]), 0.f);
        }
        #pragma unroll
        for (int it = 0; it < 8; it++){
            int kk = tid & 31, j = (tid >> 5) + it*8;
            Ws[kk][j] = w2[(c0+j)*C2 + k0 + kk];
        }
        __syncthreads();
        #pragma unroll
        for (int kk = 0; kk < 32; kk++){
            float a[4], w[4];
            #pragma unroll
            for (int u = 0; u < 4; u++){ a[u] = As[kk][ty*4+u]; w[u] = Ws[kk][tx*4+u]; }
            #pragma unroll
            for (int i = 0; i < 4; i++)
                #pragma unroll
                for (int j = 0; j < 4; j++)
                    acc[i][j] = fmaf(a[i], w[j], acc[i][j]);
        }
        __syncthreads();
    }
    #pragma unroll
    for (int i = 0; i < 4; i++){
        int n = n0 + ty*4 + i;
        #pragma unroll
        for (int j = 0; j < 4; j++){
            int c = c0 + tx*4 + j;
            size_t idx = (size_t)b*C*NPT + (size_t)c*NPT + n;
            out[idx] = x[idx] + b2[c] + acc[i][j];
        }
    }
}

// ---------------- launch ----------------
extern "C" void kernel_launch(void* const* d_in, const int* in_sizes, int n_in,
                              void* d_out, int out_size){
    const float* x     = (const float*)d_in[0];
    const float* wq    = (const float*)d_in[1];
    const float* bq    = (const float*)d_in[2];
    const float* wk    = (const float*)d_in[3];
    const float* bk    = (const float*)d_in[4];
    const float* wv    = (const float*)d_in[5];
    const float* bv    = (const float*)d_in[6];
    const float* wm    = (const float*)d_in[7];
    const float* bm    = (const float*)d_in[8];
    const float* w1    = (const float*)d_in[9];
    const float* b1    = (const float*)d_in[10];
    const float* gamma = (const float*)d_in[11];
    const float* beta  = (const float*)d_in[12];
    const float* w2    = (const float*)d_in[13];
    const float* b2    = (const float*)d_in[14];
    float* out = (float*)d_out;

    void *pbits, *psum, *psumsq;
    cudaGetSymbolAddress(&pbits,  g_bits);
    cudaGetSymbolAddress(&psum,   g_sum);
    cudaGetSymbolAddress(&psumsq, g_sumsq);
    cudaMemsetAsync(pbits,  0, sizeof(unsigned)*BB*NPT*(NPT/32), 0);
    cudaMemsetAsync(psum,   0, sizeof(float)*C2, 0);
    cudaMemsetAsync(psumsq, 0, sizeof(float)*C2, 0);

    k_xx<<<(BB*NPT + 255)/256, 256>>>(x);
    k_qkv<<<dim3(NPT/64, (3*C)/64, BB), 256>>>(x, wq, bq, wk, bk, wv, bv);
    k_gram<<<dim3(NPT/128, NPT/128, BB), 256>>>(x);
    k_topk<<<BB*NPT, 256>>>();
    k_mutual<<<(BB*NPT)/8, 256>>>();
    k_attn<<<BB*NPT, 128>>>();
    k_combine<<<C2, 128>>>(w1, b1, wm, bm);
    k_hgemm<<<dim3((BB*NPT)/64, C2/64), 256>>>(x);
    k_stats<<<(BB*NPT)/64, 256>>>();
    k_finstats<<<1, 256>>>(gamma, beta);
    k_out<<<dim3((BB*NPT)/64, C/64), 256>>>(x, w2, b2, out);
}

// round 2
// speedup vs baseline: 1.2278x; 1.2278x over previous
#include <cuda_runtime.h>
#include <math.h>

#define BB   2
#define C    128
#define NPT  2048
#define H    4
#define D    32
#define KNN  20
#define C2   256

// ---------------- scratch (device globals; no runtime alloc) ----------------
__device__ float    g_xx[BB*NPT];
__device__ float    g_q[BB*H*NPT*D];
__device__ float    g_k[BB*H*NPT*D];
__device__ float    g_v[BB*H*NPT*D];
__device__ float    g_gram[(size_t)BB*NPT*NPT];       // 33.5 MB
__device__ int      g_idx[BB*NPT*KNN];
__device__ unsigned g_bits[BB*NPT*(NPT/32)];          // knn bitsets
__device__ float    g_av[(size_t)BB*NPT*C];           // (B,N,C)
__device__ float    g_Wh[C2*C2];                      // combined [w1x | w1a@wm]
__device__ float    g_bh[C2];
__device__ float    g_h[(size_t)BB*NPT*C2];           // pre-BN h, (B*N, 2C)
__device__ float    g_sum[C2], g_sumsq[C2];
__device__ float    g_scale[C2], g_shift[C2];

// ---------------- K0: per-point squared norm ----------------
__global__ void k_xx(const float* __restrict__ x){
    int i = blockIdx.x*blockDim.x + threadIdx.x;
    if (i >= BB*NPT) return;
    int b = i / NPT, n = i % NPT;
    const float* xp = x + (size_t)b*C*NPT + n;
    float s = 0.f;
    #pragma unroll
    for (int c = 0; c < C; c++){ float v = xp[(size_t)c*NPT]; s += v*v; }
    g_xx[i] = s;
}

// ---------------- K1: fused QKV GEMM -> (B,H,N,D) layouts ----------------
__global__ __launch_bounds__(256) void k_qkv(
    const float* __restrict__ x,
    const float* __restrict__ wq, const float* __restrict__ bq,
    const float* __restrict__ wk, const float* __restrict__ bk,
    const float* __restrict__ wv, const float* __restrict__ bv)
{
    __shared__ float As[32][65];
    __shared__ float Ws[32][65];
    int b   = blockIdx.z;
    int n0  = blockIdx.x*64;
    int oc0 = blockIdx.y*64;
    int tid = threadIdx.x;
    int tx = tid & 15, ty = tid >> 4;
    float acc[4][4] = {};
    for (int k0 = 0; k0 < C; k0 += 32){
        #pragma unroll
        for (int it = 0; it < 8; it++){
            int i = tid & 63, kk = (tid >> 6) + it*4;
            As[kk][i] = x[(size_t)b*C*NPT + (size_t)(k0+kk)*NPT + n0 + i];
        }
        #pragma unroll
        for (int it = 0; it < 8; it++){
            int kk = tid & 31, j = (tid >> 5) + it*8;
            int oc = oc0 + j;
            const float* wp = (oc < C) ? wq : (oc < 2*C ? wk : wv);
            int ocl = oc & (C-1);
            Ws[kk][j] = wp[ocl*C + k0 + kk];
        }
        __syncthreads();
        #pragma unroll
        for (int kk = 0; kk < 32; kk++){
            float a[4], w[4];
            #pragma unroll
            for (int u = 0; u < 4; u++){ a[u] = As[kk][ty*4+u]; w[u] = Ws[kk][tx*4+u]; }
            #pragma unroll
            for (int i = 0; i < 4; i++)
                #pragma unroll
                for (int j = 0; j < 4; j++)
                    acc[i][j] = fmaf(a[i], w[j], acc[i][j]);
        }
        __syncthreads();
    }
    #pragma unroll
    for (int i = 0; i < 4; i++){
        int n = n0 + ty*4 + i;
        #pragma unroll
        for (int j = 0; j < 4; j++){
            int oc = oc0 + tx*4 + j;
            int t = oc >> 7, ocl = oc & (C-1);
            int h = ocl >> 5, d = ocl & 31;
            float bias = (t==0 ? bq : (t==1 ? bk : bv))[ocl];
            float* dst = (t==0 ? g_q : (t==1 ? g_k : g_v));
            dst[(((size_t)b*H + h)*NPT + n)*D + d] = acc[i][j] + bias;
        }
    }
}

// ---------------- K2a: symmetric gram GEMM (upper-triangle tiles) ----------------
// G[n,m] = 2*x_n.x_m - |x_m|^2 ; dot is symmetric -> compute tile (ti<=tj), write both.
#define NT (NPT/128)                  // 16 tiles
#define NTRI (NT*(NT+1)/2)            // 136 blocks
__global__ __launch_bounds__(256) void k_gram(const float* __restrict__ x){
    __shared__ float S[2*32*132];     // As | Bs, re-used as transpose buffer
    float (*As)[132] = (float(*)[132])S;
    float (*Bs)[132] = (float(*)[132])(S + 32*132);
    int b = blockIdx.z;
    // triangular decode
    int u = blockIdx.x, ti = 0;
    while (u >= NT - ti){ u -= NT - ti; ti++; }
    int tj = ti + u;
    int n0 = ti*128, m0 = tj*128;
    int tid = threadIdx.x;
    int tx = tid & 15, ty = tid >> 4;
    const float* xb = x + (size_t)b*C*NPT;
    float acc[8][8] = {};
    for (int k0 = 0; k0 < C; k0 += 32){
        #pragma unroll
        for (int it = 0; it < 16; it++){
            int i = tid & 127, kk = (tid >> 7) + it*2;
            As[kk][i] = xb[(size_t)(k0+kk)*NPT + n0 + i];
            Bs[kk][i] = xb[(size_t)(k0+kk)*NPT + m0 + i];
        }
        __syncthreads();
        #pragma unroll
        for (int kk = 0; kk < 32; kk++){
            float4 a0 = *(const float4*)&As[kk][ty*8];
            float4 a1 = *(const float4*)&As[kk][ty*8+4];
            float4 b0 = *(const float4*)&Bs[kk][tx*8];
            float4 b1 = *(const float4*)&Bs[kk][tx*8+4];
            float a[8] = {a0.x,a0.y,a0.z,a0.w,a1.x,a1.y,a1.z,a1.w};
            float bb[8] = {b0.x,b0.y,b0.z,b0.w,b1.x,b1.y,b1.z,b1.w};
            #pragma unroll
            for (int i = 0; i < 8; i++)
                #pragma unroll
                for (int j = 0; j < 8; j++)
                    acc[i][j] = fmaf(a[i], bb[j], acc[i][j]);
        }
        __syncthreads();
    }
    float* gp = g_gram + (size_t)b*NPT*NPT;
    const float* xxb = g_xx + b*NPT;
    // normal orientation tile: rows n, cols m (coalesced in m)
    #pragma unroll
    for (int i = 0; i < 8; i++){
        int n = n0 + ty*8 + i;
        #pragma unroll
        for (int j = 0; j < 8; j++){
            int m = m0 + tx*8 + j;
            gp[(size_t)n*NPT + m] = 2.f*acc[i][j] - xxb[m];
        }
    }
    if (ti != tj){
        // mirrored tile via shared transpose, 32 n-columns at a time
        float (*Ts)[36] = (float(*)[36])S;   // 128 x 36 floats = 18432 B, fits in S
        #pragma unroll
        for (int c = 0; c < 4; c++){
            __syncthreads();
            if ((ty >> 2) == c){
                #pragma unroll
                for (int i = 0; i < 8; i++){
                    int nl = ty*8 + i;                    // 32c .. 32c+31
                    float xn = xxb[n0 + nl];
                    #pragma unroll
                    for (int j = 0; j < 8; j++)
                        Ts[tx*8 + j][nl - c*32] = 2.f*acc[i][j] - xn;
                }
            }
            __syncthreads();
            int r = tid >> 1;
            int cl = (tid & 1)*16;
            #pragma unroll
            for (int q = 0; q < 4; q++){
                float4 t4 = *(const float4*)&Ts[r][cl + q*4];
                *(float4*)&gp[(size_t)(m0 + r)*NPT + n0 + c*32 + cl + q*4] = t4;
            }
        }
    }
}

// ---------------- K2b: top-K=20, two-phase warp extraction with REDUX ----------------
__global__ __launch_bounds__(256) void k_topk(){
    int row = blockIdx.x;                 // b*NPT + n
    const float* g = g_gram + (size_t)row*NPT;
    int tid = threadIdx.x, lane = tid & 31, wid = tid >> 5;
    __shared__ unsigned s_val[8*KNN], s_idx[8*KNN];
    unsigned v[8];
    int base = wid*256 + lane;
    #pragma unroll
    for (int j = 0; j < 8; j++){
        unsigned u = __float_as_uint(g[base + j*32]);
        u ^= (u & 0x80000000u) ? 0xFFFFFFFFu : 0x80000000u;  // orderable
        v[j] = u;
    }
    // phase 1: each warp extracts top-20 of its 256 elements (no block syncs)
    for (int r = 0; r < KNN; r++){
        unsigned b = v[0];
        #pragma unroll
        for (int j = 1; j < 8; j++) b = max(b, v[j]);
        unsigned wmax = __reduce_max_sync(0xffffffffu, b);
        unsigned ml = 0xffffffffu;
        #pragma unroll
        for (int j = 7; j >= 0; j--) if (v[j] == wmax) ml = (unsigned)(base + j*32);
        unsigned widx = __reduce_min_sync(0xffffffffu, ml);   // min index among max -> exact ref tie-break
        #pragma unroll
        for (int j = 0; j < 8; j++)
            if (v[j] == wmax && (unsigned)(base + j*32) == widx) v[j] = 0u;
        if (lane == 0){ s_val[wid*KNN + r] = wmax; s_idx[wid*KNN + r] = widx; }
    }
    __syncthreads();
    // phase 2: warp 0 merges 160 candidates
    if (wid == 0){
        unsigned v2[5], m2[5];
        #pragma unroll
        for (int t = 0; t < 5; t++){ int i = lane*5 + t; v2[t] = s_val[i]; m2[t] = s_idx[i]; }
        for (int r = 0; r < KNN; r++){
            unsigned b = v2[0];
            #pragma unroll
            for (int t = 1; t < 5; t++) b = max(b, v2[t]);
            unsigned wmax = __reduce_max_sync(0xffffffffu, b);
            unsigned ml = 0xffffffffu;
            #pragma unroll
            for (int t = 4; t >= 0; t--) if (v2[t] == wmax) ml = m2[t];
            unsigned widx = __reduce_min_sync(0xffffffffu, ml);
            #pragma unroll
            for (int t = 0; t < 5; t++)
                if (v2[t] == wmax && m2[t] == widx) v2[t] = 0u;
            if (lane == 0){
                g_idx[row*KNN + r] = (int)widx;
                atomicOr(&g_bits[(size_t)row*(NPT/32) + (widx >> 5)], 1u << (widx & 31));
            }
        }
    }
}

// ---------------- K4: mutual-mask + sparse attention (warp = head) ----------------
__global__ __launch_bounds__(128) void k_attn(){
    int row = blockIdx.x;              // b*NPT + n
    int b = row >> 11, n = row & (NPT-1);
    int tid = threadIdx.x;
    int h = tid >> 5, lane = tid & 31;
    __shared__ int adj[32]; __shared__ int scnt;
    if (tid < 32){
        int m = 0; bool ok = false;
        if (tid < KNN){
            m = g_idx[row*KNN + tid];
            ok = (g_bits[(size_t)(b*NPT + m)*(NPT/32) + (n >> 5)] >> (n & 31)) & 1u;
        }
        unsigned ball = __ballot_sync(0xffffffffu, ok);
        int pos = __popc(ball & ((1u << tid) - 1u));
        if (ok) adj[pos] = m;
        if (tid == 0) scnt = __popc(ball);
    }
    __syncthreads();
    int cnt = scnt;
    size_t hb = ((size_t)(b*H + h))*NPT*D;
    float ql = g_q[hb + (size_t)n*D + lane];
    float sc = -3.4e38f;
    for (int j = 0; j < cnt; j++){
        float pv = ql * g_k[hb + (size_t)adj[j]*D + lane];
        #pragma unroll
        for (int off = 16; off; off >>= 1) pv += __shfl_xor_sync(0xffffffffu, pv, off);
        if (lane == j) sc = pv * 0.17677669529663687f;   // 1/sqrt(32)
    }
    float mx = sc;
    #pragma unroll
    for (int off = 16; off; off >>= 1) mx = fmaxf(mx, __shfl_xor_sync(0xffffffffu, mx, off));
    float e = (lane < cnt) ? expf(sc - mx) : 0.f;
    float se = e;
    #pragma unroll
    for (int off = 16; off; off >>= 1) se += __shfl_xor_sync(0xffffffffu, se, off);
    float p = e / se;
    float acc = 0.f;
    for (int j = 0; j < cnt; j++){
        float pj = __shfl_sync(0xffffffffu, p, j);
        acc = fmaf(pj, g_v[hb + (size_t)adj[j]*D + lane], acc);
    }
    g_av[(size_t)row*C + h*D + lane] = acc;
}

// ---------------- K5a: fold wm into w1 ----------------
__global__ __launch_bounds__(128) void k_combine(
    const float* __restrict__ w1, const float* __restrict__ b1,
    const float* __restrict__ wm, const float* __restrict__ bm)
{
    int oc = blockIdx.x; int c = threadIdx.x;    // 256 blocks x 128 threads
    float s = 0.f;
    for (int c2 = 0; c2 < C; c2++)
        s = fmaf(w1[oc*C2 + C + c2], wm[c2*C + c], s);
    g_Wh[oc*C2 + C + c] = s;
    g_Wh[oc*C2 + c] = w1[oc*C2 + c];
    __shared__ float red[128];
    red[c] = w1[oc*C2 + C + c] * bm[c];
    __syncthreads();
    for (int s2 = 64; s2; s2 >>= 1){ if (c < s2) red[c] += red[c + s2]; __syncthreads(); }
    if (c == 0) g_bh[oc] = b1[oc] + red[0];
}

// ---------------- K5b: h = Wh @ [x; av] + bh  (+ fused BN stats) ----------------
__global__ __launch_bounds__(256) void k_hgemm(const float* __restrict__ x){
    __shared__ float As[32][65], Ws[32][65];
    __shared__ float cs[64], cq[64];
    int r0 = blockIdx.x*64, oc0 = blockIdx.y*64;
    int b = r0 / NPT, n0 = r0 % NPT;
    int tid = threadIdx.x, tx = tid & 15, ty = tid >> 4;
    if (tid < 64){ cs[tid] = 0.f; cq[tid] = 0.f; }
    float acc[4][4] = {};
    for (int k0 = 0; k0 < C2; k0 += 32){
        if (k0 < C){
            #pragma unroll
            for (int it = 0; it < 8; it++){
                int i = tid & 63, kk = (tid >> 6) + it*4;
                As[kk][i] = x[(size_t)b*C*NPT + (size_t)(k0+kk)*NPT + n0 + i];
            }
        } else {
            #pragma unroll
            for (int it = 0; it < 8; it++){
                int kk = tid & 31, i = (tid >> 5) + it*8;
                As[kk][i] = g_av[(size_t)(r0+i)*C + (k0 - C + kk)];
            }
        }
        #pragma unroll
        for (int it = 0; it < 8; it++){
            int kk = tid & 31, j = (tid >> 5) + it*8;
            Ws[kk][j] = g_Wh[(oc0+j)*C2 + k0 + kk];
        }
        __syncthreads();
        #pragma unroll
        for (int kk = 0; kk < 32; kk++){
            float a[4], w[4];
            #pragma unroll
            for (int u = 0; u < 4; u++){ a[u] = As[kk][ty*4+u]; w[u] = Ws[kk][tx*4+u]; }
            #pragma unroll
            for (int i = 0; i < 4; i++)
                #pragma unroll
                for (int j = 0; j < 4; j++)
                    acc[i][j] = fmaf(a[i], w[j], acc[i][j]);
        }
        __syncthreads();
    }
    float hs[4] = {}, hq[4] = {};
    #pragma unroll
    for (int i = 0; i < 4; i++){
        int r = r0 + ty*4 + i;
        #pragma unroll
        for (int j = 0; j < 4; j++){
            int oc = oc0 + tx*4 + j;
            float hv = acc[i][j] + g_bh[oc];
            g_h[(size_t)r*C2 + oc] = hv;
            hs[j] += hv; hq[j] = fmaf(hv, hv, hq[j]);
        }
    }
    #pragma unroll
    for (int j = 0; j < 4; j++){
        atomicAdd(&cs[tx*4+j], hs[j]);
        atomicAdd(&cq[tx*4+j], hq[j]);
    }
    __syncthreads();
    if (tid < 64){
        atomicAdd(&g_sum[oc0 + tid],   cs[tid]);
        atomicAdd(&g_sumsq[oc0 + tid], cq[tid]);
    }
}

// ---------------- K5c: finalize BN scale/shift ----------------
__global__ __launch_bounds__(256) void k_finstats(const float* __restrict__ gamma,
                                                  const float* __restrict__ beta){
    int oc = threadIdx.x;
    float inv = 1.f / (float)(BB*NPT);
    float mean = g_sum[oc] * inv;
    float var  = g_sumsq[oc] * inv - mean*mean;
    float rstd = 1.f / sqrtf(var + 1e-5f);
    g_scale[oc] = rstd * gamma[oc];
    g_shift[oc] = beta[oc] - mean * rstd * gamma[oc];
}

// ---------------- K5d: out = x + w2 @ relu(bn(h)) + b2 ----------------
__global__ __launch_bounds__(256) void k_out(const float* __restrict__ x,
                                             const float* __restrict__ w2,
                                             const float* __restrict__ b2,
                                             float* __restrict__ out){
    __shared__ float As[32][65], Ws[32][65];
    int r0 = blockIdx.x*64, c0 = blockIdx.y*64;
    int b = r0 / NPT, n0 = r0 % NPT;
    int tid = threadIdx.x, tx = tid & 15, ty = tid >> 4;
    float acc[4][4] = {};
    for (int k0 = 0; k0 < C2; k0 += 32){
        #pragma unroll
        for (int it = 0; it < 8; it++){
            int kk = tid & 31, i = (tid >> 5) + it*8;
            float v = g_h[(size_t)(r0+i)*C2 + k0 + kk];
            As[kk][i] = fmaxf(fmaf(v, g_scale[k0+kk], g_shift[k0+kk]), 0.f);
        }
        #pragma unroll
        for (int it = 0; it < 8; it++){
            int kk = tid & 31, j = (tid >> 5) + it*8;
            Ws[kk][j] = w2[(c0+j)*C2 + k0 + kk];
        }
        __syncthreads();
        #pragma unroll
        for (int kk = 0; kk < 32; kk++){
            float a[4], w[4];
            #pragma unroll
            for (int u = 0; u < 4; u++){ a[u] = As[kk][ty*4+u]; w[u] = Ws[kk][tx*4+u]; }
            #pragma unroll
            for (int i = 0; i < 4; i++)
                #pragma unroll
                for (int j = 0; j < 4; j++)
                    acc[i][j] = fmaf(a[i], w[j], acc[i][j]);
        }
        __syncthreads();
    }
    #pragma unroll
    for (int i = 0; i < 4; i++){
        int n = n0 + ty*4 + i;
        #pragma unroll
        for (int j = 0; j < 4; j++){
            int c = c0 + tx*4 + j;
            size_t idx = (size_t)b*C*NPT + (size_t)c*NPT + n;
            out[idx] = x[idx] + b2[c] + acc[i][j];
        }
    }
}

// ---------------- launch ----------------
extern "C" void kernel_launch(void* const* d_in, const int* in_sizes, int n_in,
                              void* d_out, int out_size){
    const float* x     = (const float*)d_in[0];
    const float* wq    = (const float*)d_in[1];
    const float* bq    = (const float*)d_in[2];
    const float* wk    = (const float*)d_in[3];
    const float* bk    = (const float*)d_in[4];
    const float* wv    = (const float*)d_in[5];
    const float* bv    = (const float*)d_in[6];
    const float* wm    = (const float*)d_in[7];
    const float* bm    = (const float*)d_in[8];
    const float* w1    = (const float*)d_in[9];
    const float* b1    = (const float*)d_in[10];
    const float* gamma = (const float*)d_in[11];
    const float* beta  = (const float*)d_in[12];
    const float* w2    = (const float*)d_in[13];
    const float* b2    = (const float*)d_in[14];
    float* out = (float*)d_out;

    void *pbits, *psum, *psumsq;
    cudaGetSymbolAddress(&pbits,  g_bits);
    cudaGetSymbolAddress(&psum,   g_sum);
    cudaGetSymbolAddress(&psumsq, g_sumsq);
    cudaMemsetAsync(pbits,  0, sizeof(unsigned)*BB*NPT*(NPT/32), 0);
    cudaMemsetAsync(psum,   0, sizeof(float)*C2, 0);
    cudaMemsetAsync(psumsq, 0, sizeof(float)*C2, 0);

    k_xx<<<(BB*NPT + 255)/256, 256>>>(x);
    k_qkv<<<dim3(NPT/64, (3*C)/64, BB), 256>>>(x, wq, bq, wk, bk, wv, bv);
    k_gram<<<dim3(NTRI, 1, BB), 256>>>(x);
    k_topk<<<BB*NPT, 256>>>();
    k_attn<<<BB*NPT, 128>>>();
    k_combine<<<C2, 128>>>(w1, b1, wm, bm);
    k_hgemm<<<dim3((BB*NPT)/64, C2/64), 256>>>(x);
    k_finstats<<<1, 256>>>(gamma, beta);
    k_out<<<dim3((BB*NPT)/64, C/64), 256>>>(x, w2, b2, out);
}

// round 3
// speedup vs baseline: 1.3238x; 1.0782x over previous
#include <cuda_runtime.h>
#include <math.h>

#define BB   2
#define C    128
#define NPT  2048
#define H    4
#define D    32
#define KNN  20
#define C2   256

// ---------------- scratch (device globals; no runtime alloc) ----------------
__device__ float    g_q[BB*H*NPT*D];
__device__ float    g_k[BB*H*NPT*D];
__device__ float    g_v[BB*H*NPT*D];
__device__ float    g_gram[(size_t)BB*NPT*NPT];       // 33.5 MB
__device__ int      g_idx[BB*NPT*KNN];
__device__ unsigned g_bits[BB*NPT*(NPT/32)];          // knn bitsets
__device__ float    g_av[(size_t)BB*NPT*C];           // (B,N,C)
__device__ float    g_Wh[C2*C2];                      // combined [w1x | w1a@wm]
__device__ float    g_bh[C2];
__device__ float    g_h[(size_t)BB*NPT*C2];           // pre-BN h, (B*N, 2C)
__device__ float    g_sum[C2], g_sumsq[C2];

#define NBW (BB*NPT*(NPT/32))                         // g_bits words

// ---------------- K1: fused QKV GEMM -> (B,H,N,D) layouts ----------------
__global__ __launch_bounds__(256) void k_qkv(
    const float* __restrict__ x,
    const float* __restrict__ wq, const float* __restrict__ bq,
    const float* __restrict__ wk, const float* __restrict__ bk,
    const float* __restrict__ wv, const float* __restrict__ bv)
{
    __shared__ float As[32][65];
    __shared__ float Ws[32][65];
    int b   = blockIdx.z;
    int n0  = blockIdx.x*64;
    int oc0 = blockIdx.y*64;
    int tid = threadIdx.x;
    int tx = tid & 15, ty = tid >> 4;
    float acc[4][4] = {};
    for (int k0 = 0; k0 < C; k0 += 32){
        #pragma unroll
        for (int it = 0; it < 8; it++){
            int i = tid & 63, kk = (tid >> 6) + it*4;
            As[kk][i] = x[(size_t)b*C*NPT + (size_t)(k0+kk)*NPT + n0 + i];
        }
        #pragma unroll
        for (int it = 0; it < 8; it++){
            int kk = tid & 31, j = (tid >> 5) + it*8;
            int oc = oc0 + j;
            const float* wp = (oc < C) ? wq : (oc < 2*C ? wk : wv);
            int ocl = oc & (C-1);
            Ws[kk][j] = wp[ocl*C + k0 + kk];
        }
        __syncthreads();
        #pragma unroll
        for (int kk = 0; kk < 32; kk++){
            float a[4], w[4];
            #pragma unroll
            for (int u = 0; u < 4; u++){ a[u] = As[kk][ty*4+u]; w[u] = Ws[kk][tx*4+u]; }
            #pragma unroll
            for (int i = 0; i < 4; i++)
                #pragma unroll
                for (int j = 0; j < 4; j++)
                    acc[i][j] = fmaf(a[i], w[j], acc[i][j]);
        }
        __syncthreads();
    }
    #pragma unroll
    for (int i = 0; i < 4; i++){
        int n = n0 + ty*4 + i;
        #pragma unroll
        for (int j = 0; j < 4; j++){
            int oc = oc0 + tx*4 + j;
            int t = oc >> 7, ocl = oc & (C-1);
            int h = ocl >> 5, d = ocl & 31;
            float bias = (t==0 ? bq : (t==1 ? bk : bv))[ocl];
            float* dst = (t==0 ? g_q : (t==1 ? g_k : g_v));
            dst[(((size_t)b*H + h)*NPT + n)*D + d] = acc[i][j] + bias;
        }
    }
}

// ---------------- K2a: symmetric gram GEMM (upper-triangle tiles) ----------------
// G[n,m] = 2*x_n.x_m - |x_m|^2 ; also zeroes g_bits and computes norms locally.
#define NT (NPT/128)                  // 16 tiles
#define NTRI (NT*(NT+1)/2)            // 136 blocks per batch
__global__ __launch_bounds__(256) void k_gram(const float* __restrict__ x){
    __shared__ float S[2*32*132];     // As | Bs, re-used as transpose buffer
    __shared__ float xxm[128], xxn[128];
    float (*As)[132] = (float(*)[132])S;
    float (*Bs)[132] = (float(*)[132])(S + 32*132);
    int b = blockIdx.z;
    int tid = threadIdx.x;

    // fold: zero a chunk of g_bits (done before k_topk runs)
    {
        int blk = b*NTRI + blockIdx.x;
        int lo = blk*964, hi = (blk+1)*964; if (hi > NBW) hi = NBW;
        for (int w = lo + tid; w < hi; w += 256) g_bits[w] = 0u;
    }

    // triangular decode
    int u = blockIdx.x, ti = 0;
    while (u >= NT - ti){ u -= NT - ti; ti++; }
    int tj = ti + u;
    int n0 = ti*128, m0 = tj*128;
    int tx = tid & 15, ty = tid >> 4;
    const float* xb = x + (size_t)b*C*NPT;

    // fold: per-block column norms (L2-resident re-reads, cheap)
    {
        int col = tid & 127;
        int base0 = (tid < 128) ? m0 : n0;
        float s = 0.f;
        #pragma unroll 4
        for (int c = 0; c < C; c++){ float v = xb[(size_t)c*NPT + base0 + col]; s = fmaf(v,v,s); }
        if (tid < 128) xxm[col] = s; else xxn[col] = s;
    }

    float acc[8][8] = {};
    for (int k0 = 0; k0 < C; k0 += 32){
        #pragma unroll
        for (int it = 0; it < 16; it++){
            int i = tid & 127, kk = (tid >> 7) + it*2;
            As[kk][i] = xb[(size_t)(k0+kk)*NPT + n0 + i];
            Bs[kk][i] = xb[(size_t)(k0+kk)*NPT + m0 + i];
        }
        __syncthreads();
        #pragma unroll
        for (int kk = 0; kk < 32; kk++){
            float4 a0 = *(const float4*)&As[kk][ty*8];
            float4 a1 = *(const float4*)&As[kk][ty*8+4];
            float4 b0 = *(const float4*)&Bs[kk][tx*8];
            float4 b1 = *(const float4*)&Bs[kk][tx*8+4];
            float a[8] = {a0.x,a0.y,a0.z,a0.w,a1.x,a1.y,a1.z,a1.w};
            float bb[8] = {b0.x,b0.y,b0.z,b0.w,b1.x,b1.y,b1.z,b1.w};
            #pragma unroll
            for (int i = 0; i < 8; i++)
                #pragma unroll
                for (int j = 0; j < 8; j++)
                    acc[i][j] = fmaf(a[i], bb[j], acc[i][j]);
        }
        __syncthreads();
    }
    float* gp = g_gram + (size_t)b*NPT*NPT;
    // normal orientation tile: rows n, cols m (coalesced in m)
    #pragma unroll
    for (int i = 0; i < 8; i++){
        int n = n0 + ty*8 + i;
        #pragma unroll
        for (int j = 0; j < 8; j++){
            int m = m0 + tx*8 + j;
            gp[(size_t)n*NPT + m] = 2.f*acc[i][j] - xxm[tx*8+j];
        }
    }
    if (ti != tj){
        // mirrored tile via shared transpose, 32 n-columns at a time
        float (*Ts)[36] = (float(*)[36])S;
        #pragma unroll
        for (int c = 0; c < 4; c++){
            __syncthreads();
            if ((ty >> 2) == c){
                #pragma unroll
                for (int i = 0; i < 8; i++){
                    int nl = ty*8 + i;
                    float xn = xxn[nl];
                    #pragma unroll
                    for (int j = 0; j < 8; j++)
                        Ts[tx*8 + j][nl - c*32] = 2.f*acc[i][j] - xn;
                }
            }
            __syncthreads();
            int r = tid >> 1;
            int cl = (tid & 1)*16;
            #pragma unroll
            for (int q = 0; q < 4; q++){
                float4 t4 = *(const float4*)&Ts[r][cl + q*4];
                *(float4*)&gp[(size_t)(m0 + r)*NPT + n0 + c*32 + cl + q*4] = t4;
            }
        }
    }
}

// ---------------- K2b: top-K=20 via 2-pass 8-bit radix select ----------------
__global__ __launch_bounds__(256) void k_topk(){
    int row = blockIdx.x;                 // b*NPT + n
    const float* g = g_gram + (size_t)row*NPT;
    int tid = threadIdx.x, lane = tid & 31;
    __shared__ int hist[256];
    __shared__ int sT, sK;
    __shared__ unsigned candV[1024];
    __shared__ int candI[1024];
    __shared__ int candCnt;

    unsigned u[8];
    {
        float4 f0 = *(const float4*)&g[tid*8];
        float4 f1 = *(const float4*)&g[tid*8+4];
        float fv[8] = {f0.x,f0.y,f0.z,f0.w,f1.x,f1.y,f1.z,f1.w};
        #pragma unroll
        for (int j = 0; j < 8; j++){
            unsigned t = __float_as_uint(fv[j]);
            u[j] = t ^ ((t & 0x80000000u) ? 0xFFFFFFFFu : 0x80000000u);
        }
    }
    hist[tid] = 0;
    if (tid == 0) candCnt = 0;
    __syncthreads();
    #pragma unroll
    for (int j = 0; j < 8; j++) atomicAdd(&hist[u[j] >> 24], 1);
    __syncthreads();
    // pass-1 suffix scan (warp 0): find byte-bin of the 20th element
    if (tid < 32){
        int c[8]; int base = lane*8; int gsum = 0;
        #pragma unroll
        for (int j = 0; j < 8; j++){ c[j] = hist[base+j]; gsum += c[j]; }
        int acc = gsum;
        #pragma unroll
        for (int off = 1; off < 32; off <<= 1){
            int o = __shfl_down_sync(0xffffffffu, acc, off);
            if (lane + off < 32) acc += o;
        }
        int suf = acc - gsum;                 // count in bins > my group
        #pragma unroll
        for (int j = 7; j >= 0; j--){
            if (suf < KNN && suf + c[j] >= KNN){ sT = base+j; sK = KNN - suf; }
            suf += c[j];
        }
    }
    __syncthreads();
    int T1 = sT, k1 = sK;
    hist[tid] = 0;
    __syncthreads();
    #pragma unroll
    for (int j = 0; j < 8; j++)
        if ((u[j] >> 24) == (unsigned)T1) atomicAdd(&hist[(u[j] >> 16) & 255], 1);
    __syncthreads();
    // pass-2 suffix scan: refine threshold to 16 bits
    if (tid < 32){
        int c[8]; int base = lane*8; int gsum = 0;
        #pragma unroll
        for (int j = 0; j < 8; j++){ c[j] = hist[base+j]; gsum += c[j]; }
        int acc = gsum;
        #pragma unroll
        for (int off = 1; off < 32; off <<= 1){
            int o = __shfl_down_sync(0xffffffffu, acc, off);
            if (lane + off < 32) acc += o;
        }
        int suf = acc - gsum;
        #pragma unroll
        for (int j = 7; j >= 0; j--){
            if (suf < k1 && suf + c[j] >= k1){ sT = base+j; }
            suf += c[j];
        }
    }
    __syncthreads();
    unsigned thr = ((unsigned)T1 << 8) | (unsigned)sT;
    #pragma unroll
    for (int j = 0; j < 8; j++){
        if ((u[j] >> 16) >= thr){
            int p = atomicAdd(&candCnt, 1);
            if (p < 1024){ candV[p] = u[j]; candI[p] = tid*8 + j; }
        }
    }
    __syncthreads();
    // exact top-20 among candidates (warp 0): max value, min index
    if (tid < 32){
        int cc = min(candCnt, 1024);
        for (int r = 0; r < KNN; r++){
            unsigned bv = 0; int bi = 0x7fffffff;
            for (int i = lane; i < cc; i += 32){
                unsigned vv = candV[i];
                if (vv > bv || (vv == bv && candI[i] < bi)){ bv = vv; bi = candI[i]; }
            }
            unsigned wm = __reduce_max_sync(0xffffffffu, bv);
            unsigned wiu = (bv == wm) ? (unsigned)bi : 0x7fffffffu;
            int wi = (int)__reduce_min_sync(0xffffffffu, wiu);
            for (int i = lane; i < cc; i += 32)
                if (candV[i] == wm && candI[i] == wi){ candV[i] = 0u; candI[i] = 0x7fffffff; }
            if (lane == 0){
                g_idx[row*KNN + r] = wi;
                atomicOr(&g_bits[(size_t)row*(NPT/32) + (wi >> 5)], 1u << (wi & 31));
            }
        }
    }
}

// ---------------- K4: mutual-mask + sparse attention (warp = head) ----------------
__global__ __launch_bounds__(128) void k_attn(){
    int row = blockIdx.x;              // b*NPT + n
    int b = row >> 11, n = row & (NPT-1);
    int tid = threadIdx.x;
    int h = tid >> 5, lane = tid & 31;
    __shared__ int adj[32]; __shared__ int scnt;
    __shared__ float sk[H][KNN][33];
    __shared__ float sv[H][KNN][33];
    __shared__ float sq[H][32];
    __shared__ float sp[H][32];
    if (tid < 32){
        int m = 0; bool ok = false;
        if (tid < KNN){
            m = g_idx[row*KNN + tid];
            ok = (g_bits[(size_t)(b*NPT + m)*(NPT/32) + (n >> 5)] >> (n & 31)) & 1u;
        }
        unsigned ball = __ballot_sync(0xffffffffu, ok);
        int pos = __popc(ball & ((1u << tid) - 1u));
        if (ok) adj[pos] = m;
        if (tid == 0) scnt = __popc(ball);
    }
    __syncthreads();
    int cnt = scnt;
    size_t hb = ((size_t)(b*H + h))*NPT*D;
    sq[h][lane] = g_q[hb + (size_t)n*D + lane];
    for (int j = 0; j < cnt; j++){
        int m = adj[j];
        sk[h][j][lane] = g_k[hb + (size_t)m*D + lane];
        sv[h][j][lane] = g_v[hb + (size_t)m*D + lane];
    }
    __syncwarp();
    // lane j owns neighbor j's score
    float s = -3.4e38f;
    if (lane < cnt){
        float a = 0.f;
        #pragma unroll 8
        for (int d = 0; d < 32; d++) a = fmaf(sq[h][d], sk[h][lane][d], a);
        s = a * 0.17677669529663687f;   // 1/sqrt(32)
    }
    float mx = s;
    #pragma unroll
    for (int off = 16; off; off >>= 1) mx = fmaxf(mx, __shfl_xor_sync(0xffffffffu, mx, off));
    float e = (lane < cnt) ? expf(s - mx) : 0.f;
    float se = e;
    #pragma unroll
    for (int off = 16; off; off >>= 1) se += __shfl_xor_sync(0xffffffffu, se, off);
    sp[h][lane] = e / se;
    __syncwarp();
    float acc = 0.f;
    for (int j = 0; j < cnt; j++)
        acc = fmaf(sp[h][j], sv[h][j][lane], acc);
    g_av[(size_t)row*C + h*D + lane] = acc;
}

// ---------------- K5a: fold wm into w1 (also zeroes BN accumulators) ----------------
__global__ __launch_bounds__(128) void k_combine(
    const float* __restrict__ w1, const float* __restrict__ b1,
    const float* __restrict__ wm, const float* __restrict__ bm)
{
    int oc = blockIdx.x; int c = threadIdx.x;    // 256 blocks x 128 threads
    if (c == 0){ g_sum[oc] = 0.f; g_sumsq[oc] = 0.f; }
    float s = 0.f;
    for (int c2 = 0; c2 < C; c2++)
        s = fmaf(w1[oc*C2 + C + c2], wm[c2*C + c], s);
    g_Wh[oc*C2 + C + c] = s;
    g_Wh[oc*C2 + c] = w1[oc*C2 + c];
    __shared__ float red[128];
    red[c] = w1[oc*C2 + C + c] * bm[c];
    __syncthreads();
    for (int s2 = 64; s2; s2 >>= 1){ if (c < s2) red[c] += red[c + s2]; __syncthreads(); }
    if (c == 0) g_bh[oc] = b1[oc] + red[0];
}

// ---------------- K5b: h = Wh @ [x; av] + bh  (+ fused BN stats) ----------------
__global__ __launch_bounds__(256) void k_hgemm(const float* __restrict__ x){
    __shared__ float As[32][65], Ws[32][65];
    __shared__ float cs[64], cq[64];
    int r0 = blockIdx.x*64, oc0 = blockIdx.y*64;
    int b = r0 / NPT, n0 = r0 % NPT;
    int tid = threadIdx.x, tx = tid & 15, ty = tid >> 4;
    if (tid < 64){ cs[tid] = 0.f; cq[tid] = 0.f; }
    float acc[4][4] = {};
    for (int k0 = 0; k0 < C2; k0 += 32){
        if (k0 < C){
            #pragma unroll
            for (int it = 0; it < 8; it++){
                int i = tid & 63, kk = (tid >> 6) + it*4;
                As[kk][i] = x[(size_t)b*C*NPT + (size_t)(k0+kk)*NPT + n0 + i];
            }
        } else {
            #pragma unroll
            for (int it = 0; it < 8; it++){
                int kk = tid & 31, i = (tid >> 5) + it*8;
                As[kk][i] = g_av[(size_t)(r0+i)*C + (k0 - C + kk)];
            }
        }
        #pragma unroll
        for (int it = 0; it < 8; it++){
            int kk = tid & 31, j = (tid >> 5) + it*8;
            Ws[kk][j] = g_Wh[(oc0+j)*C2 + k0 + kk];
        }
        __syncthreads();
        #pragma unroll
        for (int kk = 0; kk < 32; kk++){
            float a[4], w[4];
            #pragma unroll
            for (int u = 0; u < 4; u++){ a[u] = As[kk][ty*4+u]; w[u] = Ws[kk][tx*4+u]; }
            #pragma unroll
            for (int i = 0; i < 4; i++)
                #pragma unroll
                for (int j = 0; j < 4; j++)
                    acc[i][j] = fmaf(a[i], w[j], acc[i][j]);
        }
        __syncthreads();
    }
    float hs[4] = {}, hq[4] = {};
    #pragma unroll
    for (int i = 0; i < 4; i++){
        int r = r0 + ty*4 + i;
        #pragma unroll
        for (int j = 0; j < 4; j++){
            int oc = oc0 + tx*4 + j;
            float hv = acc[i][j] + g_bh[oc];
            g_h[(size_t)r*C2 + oc] = hv;
            hs[j] += hv; hq[j] = fmaf(hv, hv, hq[j]);
        }
    }
    #pragma unroll
    for (int j = 0; j < 4; j++){
        atomicAdd(&cs[tx*4+j], hs[j]);
        atomicAdd(&cq[tx*4+j], hq[j]);
    }
    __syncthreads();
    if (tid < 64){
        atomicAdd(&g_sum[oc0 + tid],   cs[tid]);
        atomicAdd(&g_sumsq[oc0 + tid], cq[tid]);
    }
}

// ---------------- K5d: out = x + w2 @ relu(bn(h)) + b2  (BN finalize fused) ----------------
__global__ __launch_bounds__(256) void k_out(const float* __restrict__ x,
                                             const float* __restrict__ w2,
                                             const float* __restrict__ b2,
                                             const float* __restrict__ gamma,
                                             const float* __restrict__ beta,
                                             float* __restrict__ out){
    __shared__ float As[32][65], Ws[32][65];
    __shared__ float ssc[C2], ssh[C2];
    int r0 = blockIdx.x*64, c0 = blockIdx.y*64;
    int b = r0 / NPT, n0 = r0 % NPT;
    int tid = threadIdx.x, tx = tid & 15, ty = tid >> 4;
    // BN finalize (redundant per block, trivial)
    {
        int oc = tid;
        float inv = 1.f / (float)(BB*NPT);
        float mean = g_sum[oc] * inv;
        float var  = g_sumsq[oc] * inv - mean*mean;
        float rstd = rsqrtf(var + 1e-5f);
        float sc = rstd * gamma[oc];
        ssc[oc] = sc;
        ssh[oc] = beta[oc] - mean * sc;
    }
    __syncthreads();
    float acc[4][4] = {};
    for (int k0 = 0; k0 < C2; k0 += 32){
        #pragma unroll
        for (int it = 0; it < 8; it++){
            int kk = tid & 31, i = (tid >> 5) + it*8;
            float v = g_h[(size_t)(r0+i)*C2 + k0 + kk];
            As[kk][i] = fmaxf(fmaf(v, ssc[k0+kk], ssh[k0+kk]), 0.f);
        }
        #pragma unroll
        for (int it = 0; it < 8; it++){
            int kk = tid & 31, j = (tid >> 5) + it*8;
            Ws[kk][j] = w2[(c0+j)*C2 + k0 + kk];
        }
        __syncthreads();
        #pragma unroll
        for (int kk = 0; kk < 32; kk++){
            float a[4], w[4];
            #pragma unroll
            for (int u = 0; u < 4; u++){ a[u] = As[kk][ty*4+u]; w[u] = Ws[kk][tx*4+u]; }
            #pragma unroll
            for (int i = 0; i < 4; i++)
                #pragma unroll
                for (int j = 0; j < 4; j++)
                    acc[i][j] = fmaf(a[i], w[j], acc[i][j]);
        }
        __syncthreads();
    }
    #pragma unroll
    for (int i = 0; i < 4; i++){
        int n = n0 + ty*4 + i;
        #pragma unroll
        for (int j = 0; j < 4; j++){
            int c = c0 + tx*4 + j;
            size_t idx = (size_t)b*C*NPT + (size_t)c*NPT + n;
            out[idx] = x[idx] + b2[c] + acc[i][j];
        }
    }
}

// ---------------- launch ----------------
extern "C" void kernel_launch(void* const* d_in, const int* in_sizes, int n_in,
                              void* d_out, int out_size){
    const float* x     = (const float*)d_in[0];
    const float* wq    = (const float*)d_in[1];
    const float* bq    = (const float*)d_in[2];
    const float* wk    = (const float*)d_in[3];
    const float* bk    = (const float*)d_in[4];
    const float* wv    = (const float*)d_in[5];
    const float* bv    = (const float*)d_in[6];
    const float* wm    = (const float*)d_in[7];
    const float* bm    = (const float*)d_in[8];
    const float* w1    = (const float*)d_in[9];
    const float* b1    = (const float*)d_in[10];
    const float* gamma = (const float*)d_in[11];
    const float* beta  = (const float*)d_in[12];
    const float* w2    = (const float*)d_in[13];
    const float* b2    = (const float*)d_in[14];
    float* out = (float*)d_out;

    k_combine<<<C2, 128>>>(w1, b1, wm, bm);
    k_qkv<<<dim3(NPT/64, (3*C)/64, BB), 256>>>(x, wq, bq, wk, bk, wv, bv);
    k_gram<<<dim3(NTRI, 1, BB), 256>>>(x);
    k_topk<<<BB*NPT, 256>>>();
    k_attn<<<BB*NPT, 128>>>();
    k_hgemm<<<dim3((BB*NPT)/64, C2/64), 256>>>(x);
    k_out<<<dim3((BB*NPT)/64, C/64), 256>>>(x, w2, b2, gamma, beta, out);
}

// round 5
// speedup vs baseline: 1.4150x; 1.0689x over previous
#include <cuda_runtime.h>
#include <math.h>

#define BB   2
#define C    128
#define NPT  2048
#define H    4
#define D    32
#define KNN  20
#define C2   256

// ---------------- scratch (device globals; no runtime alloc) ----------------
__device__ float    g_q[BB*H*NPT*D];
__device__ float    g_k[BB*H*NPT*D];
__device__ float    g_v[BB*H*NPT*D];
__device__ float    g_gram[(size_t)BB*NPT*NPT];       // 33.5 MB
__device__ int      g_idx[BB*NPT*KNN];
__device__ unsigned g_bits[BB*NPT*(NPT/32)];          // knn bitsets
__device__ float    g_av[(size_t)BB*NPT*C];           // (B,N,C)
__device__ float    g_Wh[C2*C2];                      // combined [w1x | w1a@wm]
__device__ float    g_bh[C2];
__device__ float    g_h[(size_t)BB*NPT*C2];           // pre-BN h, (B*N, 2C)
__device__ float    g_sum[C2], g_sumsq[C2];

#define NBW (BB*NPT*(NPT/32))                         // g_bits words

// ---------------- K1: fused QKV GEMM -> (B,H,N,D) layouts ----------------
__global__ __launch_bounds__(256) void k_qkv(
    const float* __restrict__ x,
    const float* __restrict__ wq, const float* __restrict__ bq,
    const float* __restrict__ wk, const float* __restrict__ bk,
    const float* __restrict__ wv, const float* __restrict__ bv)
{
    __shared__ float As[32][65];
    __shared__ float Ws[32][65];
    int b   = blockIdx.z;
    int n0  = blockIdx.x*64;
    int oc0 = blockIdx.y*64;
    int tid = threadIdx.x;
    int tx = tid & 15, ty = tid >> 4;
    float acc[4][4] = {};
    for (int k0 = 0; k0 < C; k0 += 32){
        #pragma unroll
        for (int it = 0; it < 8; it++){
            int i = tid & 63, kk = (tid >> 6) + it*4;
            As[kk][i] = x[(size_t)b*C*NPT + (size_t)(k0+kk)*NPT + n0 + i];
        }
        #pragma unroll
        for (int it = 0; it < 8; it++){
            int kk = tid & 31, j = (tid >> 5) + it*8;
            int oc = oc0 + j;
            const float* wp = (oc < C) ? wq : (oc < 2*C ? wk : wv);
            int ocl = oc & (C-1);
            Ws[kk][j] = wp[ocl*C + k0 + kk];
        }
        __syncthreads();
        #pragma unroll
        for (int kk = 0; kk < 32; kk++){
            float a[4], w[4];
            #pragma unroll
            for (int u = 0; u < 4; u++){ a[u] = As[kk][ty*4+u]; w[u] = Ws[kk][tx*4+u]; }
            #pragma unroll
            for (int i = 0; i < 4; i++)
                #pragma unroll
                for (int j = 0; j < 4; j++)
                    acc[i][j] = fmaf(a[i], w[j], acc[i][j]);
        }
        __syncthreads();
    }
    #pragma unroll
    for (int i = 0; i < 4; i++){
        int n = n0 + ty*4 + i;
        #pragma unroll
        for (int j = 0; j < 4; j++){
            int oc = oc0 + tx*4 + j;
            int t = oc >> 7, ocl = oc & (C-1);
            int h = ocl >> 5, d = ocl & 31;
            float bias = (t==0 ? bq : (t==1 ? bk : bv))[ocl];
            float* dst = (t==0 ? g_q : (t==1 ? g_k : g_v));
            dst[(((size_t)b*H + h)*NPT + n)*D + d] = acc[i][j] + bias;
        }
    }
}

// ---------------- K2a: symmetric gram GEMM (upper-triangle tiles) ----------------
#define NT (NPT/128)                  // 16 tiles
#define NTRI (NT*(NT+1)/2)            // 136 blocks per batch
__global__ __launch_bounds__(256) void k_gram(const float* __restrict__ x){
    __shared__ float S[2*32*132];     // As | Bs, re-used as transpose buffer
    __shared__ float xxm[128], xxn[128];
    float (*As)[132] = (float(*)[132])S;
    float (*Bs)[132] = (float(*)[132])(S + 32*132);
    int b = blockIdx.z;
    int tid = threadIdx.x;

    // fold: zero a chunk of g_bits (done before k_topk runs)
    {
        int blk = b*NTRI + blockIdx.x;
        int lo = blk*964, hi = (blk+1)*964; if (hi > NBW) hi = NBW;
        for (int w = lo + tid; w < hi; w += 256) g_bits[w] = 0u;
    }

    // triangular decode
    int u = blockIdx.x, ti = 0;
    while (u >= NT - ti){ u -= NT - ti; ti++; }
    int tj = ti + u;
    int n0 = ti*128, m0 = tj*128;
    int tx = tid & 15, ty = tid >> 4;
    const float* xb = x + (size_t)b*C*NPT;

    // fold: per-block column norms (L2-resident re-reads, cheap)
    {
        int col = tid & 127;
        int base0 = (tid < 128) ? m0 : n0;
        float s = 0.f;
        #pragma unroll 4
        for (int c = 0; c < C; c++){ float v = xb[(size_t)c*NPT + base0 + col]; s = fmaf(v,v,s); }
        if (tid < 128) xxm[col] = s; else xxn[col] = s;
    }

    float acc[8][8] = {};
    for (int k0 = 0; k0 < C; k0 += 32){
        #pragma unroll
        for (int it = 0; it < 16; it++){
            int i = tid & 127, kk = (tid >> 7) + it*2;
            As[kk][i] = xb[(size_t)(k0+kk)*NPT + n0 + i];
            Bs[kk][i] = xb[(size_t)(k0+kk)*NPT + m0 + i];
        }
        __syncthreads();
        #pragma unroll
        for (int kk = 0; kk < 32; kk++){
            float4 a0 = *(const float4*)&As[kk][ty*8];
            float4 a1 = *(const float4*)&As[kk][ty*8+4];
            float4 b0 = *(const float4*)&Bs[kk][tx*8];
            float4 b1 = *(const float4*)&Bs[kk][tx*8+4];
            float a[8] = {a0.x,a0.y,a0.z,a0.w,a1.x,a1.y,a1.z,a1.w};
            float bb[8] = {b0.x,b0.y,b0.z,b0.w,b1.x,b1.y,b1.z,b1.w};
            #pragma unroll
            for (int i = 0; i < 8; i++)
                #pragma unroll
                for (int j = 0; j < 8; j++)
                    acc[i][j] = fmaf(a[i], bb[j], acc[i][j]);
        }
        __syncthreads();
    }
    float* gp = g_gram + (size_t)b*NPT*NPT;
    #pragma unroll
    for (int i = 0; i < 8; i++){
        int n = n0 + ty*8 + i;
        #pragma unroll
        for (int j = 0; j < 8; j++){
            int m = m0 + tx*8 + j;
            gp[(size_t)n*NPT + m] = 2.f*acc[i][j] - xxm[tx*8+j];
        }
    }
    if (ti != tj){
        float (*Ts)[36] = (float(*)[36])S;
        #pragma unroll
        for (int c = 0; c < 4; c++){
            __syncthreads();
            if ((ty >> 2) == c){
                #pragma unroll
                for (int i = 0; i < 8; i++){
                    int nl = ty*8 + i;
                    float xn = xxn[nl];
                    #pragma unroll
                    for (int j = 0; j < 8; j++)
                        Ts[tx*8 + j][nl - c*32] = 2.f*acc[i][j] - xn;
                }
            }
            __syncthreads();
            int r = tid >> 1;
            int cl = (tid & 1)*16;
            #pragma unroll
            for (int q = 0; q < 4; q++){
                float4 t4 = *(const float4*)&Ts[r][cl + q*4];
                *(float4*)&gp[(size_t)(m0 + r)*NPT + n0 + c*32 + cl + q*4] = t4;
            }
        }
    }
}

// ---------------- K2b: top-K=20, radix select, ONE ROW PER WARP ----------------
// Register j of lane holds global element (j>>2)*128 + lane*4 + (j&3).
__global__ __launch_bounds__(256) void k_topk(){
    int wid = threadIdx.x >> 5, lane = threadIdx.x & 31;
    int row = blockIdx.x*8 + wid;
    const float* g = g_gram + (size_t)row*NPT;
    __shared__ int      hist[8][256];
    __shared__ unsigned candV[8][128];
    __shared__ int      candI[8][128];
    __shared__ int      candCnt[8];
    __shared__ int      sT1[8], sK1[8], sT2[8];
    int* h = hist[wid];

    for (int i = lane; i < 256; i += 32) h[i] = 0;
    if (lane == 0) candCnt[wid] = 0;
    __syncwarp();

    // load row (one pass), convert to orderable uint, histogram top byte
    unsigned u[64];
    #pragma unroll
    for (int t = 0; t < 16; t++){
        float4 f = *(const float4*)&g[(t*32 + lane)*4];
        unsigned a;
        a = __float_as_uint(f.x); u[t*4+0] = a ^ ((a & 0x80000000u) ? 0xFFFFFFFFu : 0x80000000u);
        a = __float_as_uint(f.y); u[t*4+1] = a ^ ((a & 0x80000000u) ? 0xFFFFFFFFu : 0x80000000u);
        a = __float_as_uint(f.z); u[t*4+2] = a ^ ((a & 0x80000000u) ? 0xFFFFFFFFu : 0x80000000u);
        a = __float_as_uint(f.w); u[t*4+3] = a ^ ((a & 0x80000000u) ? 0xFFFFFFFFu : 0x80000000u);
    }
    #pragma unroll
    for (int j = 0; j < 64; j++) atomicAdd(&h[u[j] >> 24], 1);
    __syncwarp();

    // pass-1 suffix scan: find 8-bit bin of the 20th element
    {
        int c[8]; int base = lane*8; int gsum = 0;
        #pragma unroll
        for (int j = 0; j < 8; j++){ c[j] = h[base+j]; gsum += c[j]; }
        int acc = gsum;
        #pragma unroll
        for (int off = 1; off < 32; off <<= 1){
            int o = __shfl_down_sync(0xffffffffu, acc, off);
            if (lane + off < 32) acc += o;
        }
        int suf = acc - gsum;
        #pragma unroll
        for (int j = 7; j >= 0; j--){
            if (suf < KNN && suf + c[j] >= KNN){ sT1[wid] = base+j; sK1[wid] = KNN - suf; }
            suf += c[j];
        }
    }
    __syncwarp();
    unsigned T1 = (unsigned)sT1[wid]; int k1 = sK1[wid];

    // pass-2: histogram byte 2 within bin T1
    for (int i = lane; i < 256; i += 32) h[i] = 0;
    __syncwarp();
    #pragma unroll
    for (int j = 0; j < 64; j++)
        if ((u[j] >> 24) == T1) atomicAdd(&h[(u[j] >> 16) & 255], 1);
    __syncwarp();
    {
        int c[8]; int base = lane*8; int gsum = 0;
        #pragma unroll
        for (int j = 0; j < 8; j++){ c[j] = h[base+j]; gsum += c[j]; }
        int acc = gsum;
        #pragma unroll
        for (int off = 1; off < 32; off <<= 1){
            int o = __shfl_down_sync(0xffffffffu, acc, off);
            if (lane + off < 32) acc += o;
        }
        int suf = acc - gsum;
        #pragma unroll
        for (int j = 7; j >= 0; j--){
            if (suf < k1 && suf + c[j] >= k1){ sT2[wid] = base+j; }
            suf += c[j];
        }
    }
    __syncwarp();
    unsigned thr = (T1 << 8) | (unsigned)sT2[wid];

    // collect candidates (>= 16-bit threshold; superset of exact top-20)
    #pragma unroll
    for (int j = 0; j < 64; j++){
        if ((u[j] >> 16) >= thr){
            int p = atomicAdd(&candCnt[wid], 1);
            if (p < 128){
                candV[wid][p] = u[j];
                candI[wid][p] = (j >> 2)*128 + lane*4 + (j & 3);   // FIXED index map
            }
        }
    }
    __syncwarp();

    // exact top-20 among candidates (max value, min index — matches lax.top_k)
    int cc = min(candCnt[wid], 128);
    for (int r = 0; r < KNN; r++){
        unsigned bv = 0; int bi = 0x7fffffff;
        for (int i = lane; i < cc; i += 32){
            unsigned vv = candV[wid][i];
            if (vv > bv || (vv == bv && candI[wid][i] < bi)){ bv = vv; bi = candI[wid][i]; }
        }
        unsigned wm = __reduce_max_sync(0xffffffffu, bv);
        unsigned wiu = (bv == wm) ? (unsigned)bi : 0x7fffffffu;
        int wi = (int)__reduce_min_sync(0xffffffffu, wiu);
        for (int i = lane; i < cc; i += 32)
            if (candV[wid][i] == wm && candI[wid][i] == wi){ candV[wid][i] = 0u; candI[wid][i] = 0x7fffffff; }
        if (lane == 0){
            g_idx[row*KNN + r] = wi;
            atomicOr(&g_bits[(size_t)row*(NPT/32) + (wi >> 5)], 1u << (wi & 31));
        }
    }
}

// ---------------- K4: mutual-mask + sparse attention (warp = head) ----------------
__global__ __launch_bounds__(128) void k_attn(){
    int row = blockIdx.x;              // b*NPT + n
    int b = row >> 11, n = row & (NPT-1);
    int tid = threadIdx.x;
    int h = tid >> 5, lane = tid & 31;
    __shared__ int adj[32]; __shared__ int scnt;
    __shared__ float sk[H][KNN][33];
    __shared__ float sv[H][KNN][33];
    __shared__ float sq[H][32];
    __shared__ float sp[H][32];
    if (tid < 32){
        int m = 0; bool ok = false;
        if (tid < KNN){
            m = g_idx[row*KNN + tid];
            ok = (g_bits[(size_t)(b*NPT + m)*(NPT/32) + (n >> 5)] >> (n & 31)) & 1u;
        }
        unsigned ball = __ballot_sync(0xffffffffu, ok);
        int pos = __popc(ball & ((1u << tid) - 1u));
        if (ok) adj[pos] = m;
        if (tid == 0) scnt = __popc(ball);
    }
    __syncthreads();
    int cnt = scnt;
    size_t hb = ((size_t)(b*H + h))*NPT*D;
    sq[h][lane] = g_q[hb + (size_t)n*D + lane];
    for (int j = 0; j < cnt; j++){
        int m = adj[j];
        sk[h][j][lane] = g_k[hb + (size_t)m*D + lane];
        sv[h][j][lane] = g_v[hb + (size_t)m*D + lane];
    }
    __syncwarp();
    float s = -3.4e38f;
    if (lane < cnt){
        float a = 0.f;
        #pragma unroll 8
        for (int d = 0; d < 32; d++) a = fmaf(sq[h][d], sk[h][lane][d], a);
        s = a * 0.17677669529663687f;   // 1/sqrt(32)
    }
    float mx = s;
    #pragma unroll
    for (int off = 16; off; off >>= 1) mx = fmaxf(mx, __shfl_xor_sync(0xffffffffu, mx, off));
    float e = (lane < cnt) ? expf(s - mx) : 0.f;
    float se = e;
    #pragma unroll
    for (int off = 16; off; off >>= 1) se += __shfl_xor_sync(0xffffffffu, se, off);
    sp[h][lane] = e / se;
    __syncwarp();
    float acc = 0.f;
    for (int j = 0; j < cnt; j++)
        acc = fmaf(sp[h][j], sv[h][j][lane], acc);
    g_av[(size_t)row*C + h*D + lane] = acc;
}

// ---------------- K5a: fold wm into w1 (also zeroes BN accumulators) ----------------
__global__ __launch_bounds__(128) void k_combine(
    const float* __restrict__ w1, const float* __restrict__ b1,
    const float* __restrict__ wm, const float* __restrict__ bm)
{
    int oc = blockIdx.x; int c = threadIdx.x;    // 256 blocks x 128 threads
    if (c == 0){ g_sum[oc] = 0.f; g_sumsq[oc] = 0.f; }
    float s = 0.f;
    for (int c2 = 0; c2 < C; c2++)
        s = fmaf(w1[oc*C2 + C + c2], wm[c2*C + c], s);
    g_Wh[oc*C2 + C + c] = s;
    g_Wh[oc*C2 + c] = w1[oc*C2 + c];
    __shared__ float red[128];
    red[c] = w1[oc*C2 + C + c] * bm[c];
    __syncthreads();
    for (int s2 = 64; s2; s2 >>= 1){ if (c < s2) red[c] += red[c + s2]; __syncthreads(); }
    if (c == 0) g_bh[oc] = b1[oc] + red[0];
}

// ---------------- K5b: h = Wh @ [x; av] + bh  (+ fused BN stats) ----------------
__global__ __launch_bounds__(256) void k_hgemm(const float* __restrict__ x){
    __shared__ float As[32][65], Ws[32][65];
    __shared__ float cs[64], cq[64];
    int r0 = blockIdx.x*64, oc0 = blockIdx.y*64;
    int b = r0 / NPT, n0 = r0 % NPT;
    int tid = threadIdx.x, tx = tid & 15, ty = tid >> 4;
    if (tid < 64){ cs[tid] = 0.f; cq[tid] = 0.f; }
    float acc[4][4] = {};
    for (int k0 = 0; k0 < C2; k0 += 32){
        if (k0 < C){
            #pragma unroll
            for (int it = 0; it < 8; it++){
                int i = tid & 63, kk = (tid >> 6) + it*4;
                As[kk][i] = x[(size_t)b*C*NPT + (size_t)(k0+kk)*NPT + n0 + i];
            }
        } else {
            #pragma unroll
            for (int it = 0; it < 8; it++){
                int kk = tid & 31, i = (tid >> 5) + it*8;
                As[kk][i] = g_av[(size_t)(r0+i)*C + (k0 - C + kk)];
            }
        }
        #pragma unroll
        for (int it = 0; it < 8; it++){
            int kk = tid & 31, j = (tid >> 5) + it*8;
            Ws[kk][j] = g_Wh[(oc0+j)*C2 + k0 + kk];
        }
        __syncthreads();
        #pragma unroll
        for (int kk = 0; kk < 32; kk++){
            float a[4], w[4];
            #pragma unroll
            for (int u = 0; u < 4; u++){ a[u] = As[kk][ty*4+u]; w[u] = Ws[kk][tx*4+u]; }
            #pragma unroll
            for (int i = 0; i < 4; i++)
                #pragma unroll
                for (int j = 0; j < 4; j++)
                    acc[i][j] = fmaf(a[i], w[j], acc[i][j]);
        }
        __syncthreads();
    }
    float hs[4] = {}, hq[4] = {};
    #pragma unroll
    for (int i = 0; i < 4; i++){
        int r = r0 + ty*4 + i;
        #pragma unroll
        for (int j = 0; j < 4; j++){
            int oc = oc0 + tx*4 + j;
            float hv = acc[i][j] + g_bh[oc];
            g_h[(size_t)r*C2 + oc] = hv;
            hs[j] += hv; hq[j] = fmaf(hv, hv, hq[j]);
        }
    }
    #pragma unroll
    for (int j = 0; j < 4; j++){
        atomicAdd(&cs[tx*4+j], hs[j]);
        atomicAdd(&cq[tx*4+j], hq[j]);
    }
    __syncthreads();
    if (tid < 64){
        atomicAdd(&g_sum[oc0 + tid],   cs[tid]);
        atomicAdd(&g_sumsq[oc0 + tid], cq[tid]);
    }
}

// ---------------- K5d: out = x + w2 @ relu(bn(h)) + b2  (BN finalize fused) ----------------
__global__ __launch_bounds__(256) void k_out(const float* __restrict__ x,
                                             const float* __restrict__ w2,
                                             const float* __restrict__ b2,
                                             const float* __restrict__ gamma,
                                             const float* __restrict__ beta,
                                             float* __restrict__ out){
    __shared__ float As[32][65], Ws[32][65];
    __shared__ float ssc[C2], ssh[C2];
    int r0 = blockIdx.x*64, c0 = blockIdx.y*64;
    int b = r0 / NPT, n0 = r0 % NPT;
    int tid = threadIdx.x, tx = tid & 15, ty = tid >> 4;
    {
        int oc = tid;
        float inv = 1.f / (float)(BB*NPT);
        float mean = g_sum[oc] * inv;
        float var  = g_sumsq[oc] * inv - mean*mean;
        float rstd = rsqrtf(var + 1e-5f);
        float sc = rstd * gamma[oc];
        ssc[oc] = sc;
        ssh[oc] = beta[oc] - mean * sc;
    }
    __syncthreads();
    float acc[4][4] = {};
    for (int k0 = 0; k0 < C2; k0 += 32){
        #pragma unroll
        for (int it = 0; it < 8; it++){
            int kk = tid & 31, i = (tid >> 5) + it*8;
            float v = g_h[(size_t)(r0+i)*C2 + k0 + kk];
            As[kk][i] = fmaxf(fmaf(v, ssc[k0+kk], ssh[k0+kk]), 0.f);
        }
        #pragma unroll
        for (int it = 0; it < 8; it++){
            int kk = tid & 31, j = (tid >> 5) + it*8;
            Ws[kk][j] = w2[(c0+j)*C2 + k0 + kk];
        }
        __syncthreads();
        #pragma unroll
        for (int kk = 0; kk < 32; kk++){
            float a[4], w[4];
            #pragma unroll
            for (int u = 0; u < 4; u++){ a[u] = As[kk][ty*4+u]; w[u] = Ws[kk][tx*4+u]; }
            #pragma unroll
            for (int i = 0; i < 4; i++)
                #pragma unroll
                for (int j = 0; j < 4; j++)
                    acc[i][j] = fmaf(a[i], w[j], acc[i][j]);
        }
        __syncthreads();
    }
    #pragma unroll
    for (int i = 0; i < 4; i++){
        int n = n0 + ty*4 + i;
        #pragma unroll
        for (int j = 0; j < 4; j++){
            int c = c0 + tx*4 + j;
            size_t idx = (size_t)b*C*NPT + (size_t)c*NPT + n;
            out[idx] = x[idx] + b2[c] + acc[i][j];
        }
    }
}

// ---------------- launch ----------------
extern "C" void kernel_launch(void* const* d_in, const int* in_sizes, int n_in,
                              void* d_out, int out_size){
    const float* x     = (const float*)d_in[0];
    const float* wq    = (const float*)d_in[1];
    const float* bq    = (const float*)d_in[2];
    const float* wk    = (const float*)d_in[3];
    const float* bk    = (const float*)d_in[4];
    const float* wv    = (const float*)d_in[5];
    const float* bv    = (const float*)d_in[6];
    const float* wm    = (const float*)d_in[7];
    const float* bm    = (const float*)d_in[8];
    const float* w1    = (const float*)d_in[9];
    const float* b1    = (const float*)d_in[10];
    const float* gamma = (const float*)d_in[11];
    const float* beta  = (const float*)d_in[12];
    const float* w2    = (const float*)d_in[13];
    const float* b2    = (const float*)d_in[14];
    float* out = (float*)d_out;

    k_combine<<<C2, 128>>>(w1, b1, wm, bm);
    k_qkv<<<dim3(NPT/64, (3*C)/64, BB), 256>>>(x, wq, bq, wk, bk, wv, bv);
    k_gram<<<dim3(NTRI, 1, BB), 256>>>(x);
    k_topk<<<(BB*NPT)/8, 256>>>();
    k_attn<<<BB*NPT, 128>>>();
    k_hgemm<<<dim3((BB*NPT)/64, C2/64), 256>>>(x);
    k_out<<<dim3((BB*NPT)/64, C/64), 256>>>(x, w2, b2, gamma, beta, out);
}

// round 6
// speedup vs baseline: 1.4478x; 1.0231x over previous
#include <cuda_runtime.h>
#include <math.h>

#define BB   2
#define C    128
#define NPT  2048
#define H    4
#define D    32
#define KNN  20
#define C2   256

// ---------------- scratch (device globals; no runtime alloc) ----------------
__device__ float    g_q[BB*H*NPT*D];
__device__ float    g_k[BB*H*NPT*D];
__device__ float    g_v[BB*H*NPT*D];
__device__ float    g_gram[(size_t)BB*NPT*NPT];       // 33.5 MB (L2-resident)
__device__ int      g_idx[BB*NPT*KNN];
__device__ unsigned g_bits[BB*NPT*(NPT/32)];          // knn bitsets
__device__ float    g_av[(size_t)BB*NPT*C];           // (B,N,C)
__device__ float    g_Wh[C2*C2];                      // combined [w1x | w1a@wm]
__device__ float    g_bh[C2];
__device__ float    g_h[(size_t)BB*NPT*C2];           // pre-BN h, (B*N, 2C)
__device__ float    g_sum[C2], g_sumsq[C2];

#define NBW (BB*NPT*(NPT/32))                         // g_bits words

// ---------------- K1: fused QKV GEMM -> (B,H,N,D) layouts ----------------
__global__ __launch_bounds__(256) void k_qkv(
    const float* __restrict__ x,
    const float* __restrict__ wq, const float* __restrict__ bq,
    const float* __restrict__ wk, const float* __restrict__ bk,
    const float* __restrict__ wv, const float* __restrict__ bv)
{
    __shared__ float As[32][65];
    __shared__ float Ws[32][65];
    int b   = blockIdx.z;
    int n0  = blockIdx.x*64;
    int oc0 = blockIdx.y*64;
    int tid = threadIdx.x;
    int tx = tid & 15, ty = tid >> 4;
    float acc[4][4] = {};
    for (int k0 = 0; k0 < C; k0 += 32){
        #pragma unroll
        for (int it = 0; it < 8; it++){
            int i = tid & 63, kk = (tid >> 6) + it*4;
            As[kk][i] = x[(size_t)b*C*NPT + (size_t)(k0+kk)*NPT + n0 + i];
        }
        #pragma unroll
        for (int it = 0; it < 8; it++){
            int kk = tid & 31, j = (tid >> 5) + it*8;
            int oc = oc0 + j;
            const float* wp = (oc < C) ? wq : (oc < 2*C ? wk : wv);
            int ocl = oc & (C-1);
            Ws[kk][j] = wp[ocl*C + k0 + kk];
        }
        __syncthreads();
        #pragma unroll
        for (int kk = 0; kk < 32; kk++){
            float a[4], w[4];
            #pragma unroll
            for (int u = 0; u < 4; u++){ a[u] = As[kk][ty*4+u]; w[u] = Ws[kk][tx*4+u]; }
            #pragma unroll
            for (int i = 0; i < 4; i++)
                #pragma unroll
                for (int j = 0; j < 4; j++)
                    acc[i][j] = fmaf(a[i], w[j], acc[i][j]);
        }
        __syncthreads();
    }
    #pragma unroll
    for (int i = 0; i < 4; i++){
        int n = n0 + ty*4 + i;
        #pragma unroll
        for (int j = 0; j < 4; j++){
            int oc = oc0 + tx*4 + j;
            int t = oc >> 7, ocl = oc & (C-1);
            int h = ocl >> 5, d = ocl & 31;
            float bias = (t==0 ? bq : (t==1 ? bk : bv))[ocl];
            float* dst = (t==0 ? g_q : (t==1 ? g_k : g_v));
            dst[(((size_t)b*H + h)*NPT + n)*D + d] = acc[i][j] + bias;
        }
    }
}

// ---------------- K2a: symmetric gram GEMM (upper-triangle tiles) ----------------
#define NT (NPT/128)                  // 16 tiles
#define NTRI (NT*(NT+1)/2)            // 136 blocks per batch
__global__ __launch_bounds__(256) void k_gram(const float* __restrict__ x){
    __shared__ float S[2*32*132];     // As | Bs, re-used as transpose buffer
    __shared__ float xxm[128], xxn[128];
    float (*As)[132] = (float(*)[132])S;
    float (*Bs)[132] = (float(*)[132])(S + 32*132);
    int b = blockIdx.z;
    int tid = threadIdx.x;

    // fold: zero a chunk of g_bits (done before k_topk runs)
    {
        int blk = b*NTRI + blockIdx.x;
        int lo = blk*964, hi = (blk+1)*964; if (hi > NBW) hi = NBW;
        for (int w = lo + tid; w < hi; w += 256) g_bits[w] = 0u;
    }

    // triangular decode
    int u = blockIdx.x, ti = 0;
    while (u >= NT - ti){ u -= NT - ti; ti++; }
    int tj = ti + u;
    int n0 = ti*128, m0 = tj*128;
    int tx = tid & 15, ty = tid >> 4;
    const float* xb = x + (size_t)b*C*NPT;

    // fold: per-block column norms (L2-resident re-reads, cheap)
    {
        int col = tid & 127;
        int base0 = (tid < 128) ? m0 : n0;
        float s = 0.f;
        #pragma unroll 4
        for (int c = 0; c < C; c++){ float v = xb[(size_t)c*NPT + base0 + col]; s = fmaf(v,v,s); }
        if (tid < 128) xxm[col] = s; else xxn[col] = s;
    }

    float acc[8][8] = {};
    for (int k0 = 0; k0 < C; k0 += 32){
        #pragma unroll
        for (int it = 0; it < 16; it++){
            int i = tid & 127, kk = (tid >> 7) + it*2;
            As[kk][i] = xb[(size_t)(k0+kk)*NPT + n0 + i];
            Bs[kk][i] = xb[(size_t)(k0+kk)*NPT + m0 + i];
        }
        __syncthreads();
        #pragma unroll
        for (int kk = 0; kk < 32; kk++){
            float4 a0 = *(const float4*)&As[kk][ty*8];
            float4 a1 = *(const float4*)&As[kk][ty*8+4];
            float4 b0 = *(const float4*)&Bs[kk][tx*8];
            float4 b1 = *(const float4*)&Bs[kk][tx*8+4];
            float a[8] = {a0.x,a0.y,a0.z,a0.w,a1.x,a1.y,a1.z,a1.w};
            float bb[8] = {b0.x,b0.y,b0.z,b0.w,b1.x,b1.y,b1.z,b1.w};
            #pragma unroll
            for (int i = 0; i < 8; i++)
                #pragma unroll
                for (int j = 0; j < 8; j++)
                    acc[i][j] = fmaf(a[i], bb[j], acc[i][j]);
        }
        __syncthreads();
    }
    float* gp = g_gram + (size_t)b*NPT*NPT;
    #pragma unroll
    for (int i = 0; i < 8; i++){
        int n = n0 + ty*8 + i;
        #pragma unroll
        for (int j = 0; j < 8; j++){
            int m = m0 + tx*8 + j;
            gp[(size_t)n*NPT + m] = 2.f*acc[i][j] - xxm[tx*8+j];
        }
    }
    if (ti != tj){
        float (*Ts)[36] = (float(*)[36])S;
        #pragma unroll
        for (int c = 0; c < 4; c++){
            __syncthreads();
            if ((ty >> 2) == c){
                #pragma unroll
                for (int i = 0; i < 8; i++){
                    int nl = ty*8 + i;
                    float xn = xxn[nl];
                    #pragma unroll
                    for (int j = 0; j < 8; j++)
                        Ts[tx*8 + j][nl - c*32] = 2.f*acc[i][j] - xn;
                }
            }
            __syncthreads();
            int r = tid >> 1;
            int cl = (tid & 1)*16;
            #pragma unroll
            for (int q = 0; q < 4; q++){
                float4 t4 = *(const float4*)&Ts[r][cl + q*4];
                *(float4*)&gp[(size_t)(m0 + r)*NPT + n0 + c*32 + cl + q*4] = t4;
            }
        }
    }
}

// ---------------- K2b: top-K=20, radix select, ONE ROW PER WARP ----------------
// Streaming version: row is re-read from L2 per pass (low registers, high occ).
__device__ __forceinline__ unsigned f2ord(float f){
    unsigned a = __float_as_uint(f);
    return a ^ ((a & 0x80000000u) ? 0xFFFFFFFFu : 0x80000000u);
}
__global__ __launch_bounds__(256) void k_topk(){
    int wid = threadIdx.x >> 5, lane = threadIdx.x & 31;
    int row = blockIdx.x*8 + wid;
    const float4* g4 = (const float4*)(g_gram + (size_t)row*NPT);
    __shared__ int      hist[8][256];
    __shared__ unsigned candV[8][128];
    __shared__ int      candI[8][128];
    __shared__ int      candCnt[8];
    __shared__ int      sT1[8], sK1[8], sT2[8];
    int* h = hist[wid];

    for (int i = lane; i < 256; i += 32) h[i] = 0;
    if (lane == 0) candCnt[wid] = 0;
    __syncwarp();

    // pass 1: byte-3 histogram (streaming)
    #pragma unroll 4
    for (int t = 0; t < 16; t++){
        float4 f = g4[t*32 + lane];
        atomicAdd(&h[f2ord(f.x) >> 24], 1);
        atomicAdd(&h[f2ord(f.y) >> 24], 1);
        atomicAdd(&h[f2ord(f.z) >> 24], 1);
        atomicAdd(&h[f2ord(f.w) >> 24], 1);
    }
    __syncwarp();
    {
        int c[8]; int base = lane*8; int gsum = 0;
        #pragma unroll
        for (int j = 0; j < 8; j++){ c[j] = h[base+j]; gsum += c[j]; }
        int acc = gsum;
        #pragma unroll
        for (int off = 1; off < 32; off <<= 1){
            int o = __shfl_down_sync(0xffffffffu, acc, off);
            if (lane + off < 32) acc += o;
        }
        int suf = acc - gsum;
        #pragma unroll
        for (int j = 7; j >= 0; j--){
            if (suf < KNN && suf + c[j] >= KNN){ sT1[wid] = base+j; sK1[wid] = KNN - suf; }
            suf += c[j];
        }
    }
    __syncwarp();
    unsigned T1 = (unsigned)sT1[wid]; int k1 = sK1[wid];

    // pass 2: byte-2 histogram within bin T1 (streaming)
    for (int i = lane; i < 256; i += 32) h[i] = 0;
    __syncwarp();
    #pragma unroll 4
    for (int t = 0; t < 16; t++){
        float4 f = g4[t*32 + lane];
        unsigned a;
        a = f2ord(f.x); if ((a >> 24) == T1) atomicAdd(&h[(a >> 16) & 255], 1);
        a = f2ord(f.y); if ((a >> 24) == T1) atomicAdd(&h[(a >> 16) & 255], 1);
        a = f2ord(f.z); if ((a >> 24) == T1) atomicAdd(&h[(a >> 16) & 255], 1);
        a = f2ord(f.w); if ((a >> 24) == T1) atomicAdd(&h[(a >> 16) & 255], 1);
    }
    __syncwarp();
    {
        int c[8]; int base = lane*8; int gsum = 0;
        #pragma unroll
        for (int j = 0; j < 8; j++){ c[j] = h[base+j]; gsum += c[j]; }
        int acc = gsum;
        #pragma unroll
        for (int off = 1; off < 32; off <<= 1){
            int o = __shfl_down_sync(0xffffffffu, acc, off);
            if (lane + off < 32) acc += o;
        }
        int suf = acc - gsum;
        #pragma unroll
        for (int j = 7; j >= 0; j--){
            if (suf < k1 && suf + c[j] >= k1){ sT2[wid] = base+j; }
            suf += c[j];
        }
    }
    __syncwarp();
    unsigned thr = (T1 << 8) | (unsigned)sT2[wid];

    // pass 3: collect candidates >= 16-bit threshold (superset of exact top-20)
    #pragma unroll 4
    for (int t = 0; t < 16; t++){
        float4 f = g4[t*32 + lane];
        int base = (t*32 + lane)*4;
        unsigned a;
        a = f2ord(f.x);
        if ((a >> 16) >= thr){ int p = atomicAdd(&candCnt[wid],1); if (p<128){ candV[wid][p]=a; candI[wid][p]=base+0; } }
        a = f2ord(f.y);
        if ((a >> 16) >= thr){ int p = atomicAdd(&candCnt[wid],1); if (p<128){ candV[wid][p]=a; candI[wid][p]=base+1; } }
        a = f2ord(f.z);
        if ((a >> 16) >= thr){ int p = atomicAdd(&candCnt[wid],1); if (p<128){ candV[wid][p]=a; candI[wid][p]=base+2; } }
        a = f2ord(f.w);
        if ((a >> 16) >= thr){ int p = atomicAdd(&candCnt[wid],1); if (p<128){ candV[wid][p]=a; candI[wid][p]=base+3; } }
    }
    __syncwarp();

    // exact top-20 among candidates (max value, min index — matches lax.top_k)
    int cc = min(candCnt[wid], 128);
    for (int r = 0; r < KNN; r++){
        unsigned bv = 0; int bi = 0x7fffffff;
        for (int i = lane; i < cc; i += 32){
            unsigned vv = candV[wid][i];
            if (vv > bv || (vv == bv && candI[wid][i] < bi)){ bv = vv; bi = candI[wid][i]; }
        }
        unsigned wm = __reduce_max_sync(0xffffffffu, bv);
        unsigned wiu = (bv == wm) ? (unsigned)bi : 0x7fffffffu;
        int wi = (int)__reduce_min_sync(0xffffffffu, wiu);
        for (int i = lane; i < cc; i += 32)
            if (candV[wid][i] == wm && candI[wid][i] == wi){ candV[wid][i] = 0u; candI[wid][i] = 0x7fffffff; }
        if (lane == 0){
            g_idx[row*KNN + r] = wi;
            atomicOr(&g_bits[(size_t)row*(NPT/32) + (wi >> 5)], 1u << (wi & 31));
        }
    }
}

// ---------------- K4: mutual-mask + sparse attention (warp = head) ----------------
__global__ __launch_bounds__(128) void k_attn(){
    int row = blockIdx.x;              // b*NPT + n
    int b = row >> 11, n = row & (NPT-1);
    int tid = threadIdx.x;
    int h = tid >> 5, lane = tid & 31;
    __shared__ int adj[32]; __shared__ int scnt;
    __shared__ float sk[H][KNN][33];
    __shared__ float sv[H][KNN][33];
    __shared__ float sq[H][32];
    __shared__ float sp[H][32];
    if (tid < 32){
        int m = 0; bool ok = false;
        if (tid < KNN){
            m = g_idx[row*KNN + tid];
            ok = (g_bits[(size_t)(b*NPT + m)*(NPT/32) + (n >> 5)] >> (n & 31)) & 1u;
        }
        unsigned ball = __ballot_sync(0xffffffffu, ok);
        int pos = __popc(ball & ((1u << tid) - 1u));
        if (ok) adj[pos] = m;
        if (tid == 0) scnt = __popc(ball);
    }
    __syncthreads();
    int cnt = scnt;
    size_t hb = ((size_t)(b*H + h))*NPT*D;
    sq[h][lane] = g_q[hb + (size_t)n*D + lane];
    for (int j = 0; j < cnt; j++){
        int m = adj[j];
        sk[h][j][lane] = g_k[hb + (size_t)m*D + lane];
        sv[h][j][lane] = g_v[hb + (size_t)m*D + lane];
    }
    __syncwarp();
    float s = -3.4e38f;
    if (lane < cnt){
        float a = 0.f;
        #pragma unroll 8
        for (int d = 0; d < 32; d++) a = fmaf(sq[h][d], sk[h][lane][d], a);
        s = a * 0.17677669529663687f;   // 1/sqrt(32)
    }
    float mx = s;
    #pragma unroll
    for (int off = 16; off; off >>= 1) mx = fmaxf(mx, __shfl_xor_sync(0xffffffffu, mx, off));
    float e = (lane < cnt) ? expf(s - mx) : 0.f;
    float se = e;
    #pragma unroll
    for (int off = 16; off; off >>= 1) se += __shfl_xor_sync(0xffffffffu, se, off);
    sp[h][lane] = e / se;
    __syncwarp();
    float acc = 0.f;
    for (int j = 0; j < cnt; j++)
        acc = fmaf(sp[h][j], sv[h][j][lane], acc);
    g_av[(size_t)row*C + h*D + lane] = acc;
}

// ---------------- K5a: fold wm into w1 (also zeroes BN accumulators) ----------------
__global__ __launch_bounds__(128) void k_combine(
    const float* __restrict__ w1, const float* __restrict__ b1,
    const float* __restrict__ wm, const float* __restrict__ bm)
{
    int oc = blockIdx.x; int c = threadIdx.x;    // 256 blocks x 128 threads
    if (c == 0){ g_sum[oc] = 0.f; g_sumsq[oc] = 0.f; }
    float s = 0.f;
    for (int c2 = 0; c2 < C; c2++)
        s = fmaf(w1[oc*C2 + C + c2], wm[c2*C + c], s);
    g_Wh[oc*C2 + C + c] = s;
    g_Wh[oc*C2 + c] = w1[oc*C2 + c];
    __shared__ float red[128];
    red[c] = w1[oc*C2 + C + c] * bm[c];
    __syncthreads();
    for (int s2 = 64; s2; s2 >>= 1){ if (c < s2) red[c] += red[c + s2]; __syncthreads(); }
    if (c == 0) g_bh[oc] = b1[oc] + red[0];
}

// ---------------- K5b: h = Wh @ [x; av] + bh  (+ fused BN stats) ----------------
__global__ __launch_bounds__(256) void k_hgemm(const float* __restrict__ x){
    __shared__ float As[32][65], Ws[32][65];
    __shared__ float cs[64], cq[64];
    int r0 = blockIdx.x*64, oc0 = blockIdx.y*64;
    int b = r0 / NPT, n0 = r0 % NPT;
    int tid = threadIdx.x, tx = tid & 15, ty = tid >> 4;
    if (tid < 64){ cs[tid] = 0.f; cq[tid] = 0.f; }
    float acc[4][4] = {};
    for (int k0 = 0; k0 < C2; k0 += 32){
        if (k0 < C){
            #pragma unroll
            for (int it = 0; it < 8; it++){
                int i = tid & 63, kk = (tid >> 6) + it*4;
                As[kk][i] = x[(size_t)b*C*NPT + (size_t)(k0+kk)*NPT + n0 + i];
            }
        } else {
            #pragma unroll
            for (int it = 0; it < 8; it++){
                int kk = tid & 31, i = (tid >> 5) + it*8;
                As[kk][i] = g_av[(size_t)(r0+i)*C + (k0 - C + kk)];
            }
        }
        #pragma unroll
        for (int it = 0; it < 8; it++){
            int kk = tid & 31, j = (tid >> 5) + it*8;
            Ws[kk][j] = g_Wh[(oc0+j)*C2 + k0 + kk];
        }
        __syncthreads();
        #pragma unroll
        for (int kk = 0; kk < 32; kk++){
            float a[4], w[4];
            #pragma unroll
            for (int u = 0; u < 4; u++){ a[u] = As[kk][ty*4+u]; w[u] = Ws[kk][tx*4+u]; }
            #pragma unroll
            for (int i = 0; i < 4; i++)
                #pragma unroll
                for (int j = 0; j < 4; j++)
                    acc[i][j] = fmaf(a[i], w[j], acc[i][j]);
        }
        __syncthreads();
    }
    float hs[4] = {}, hq[4] = {};
    #pragma unroll
    for (int i = 0; i < 4; i++){
        int r = r0 + ty*4 + i;
        #pragma unroll
        for (int j = 0; j < 4; j++){
            int oc = oc0 + tx*4 + j;
            float hv = acc[i][j] + g_bh[oc];
            g_h[(size_t)r*C2 + oc] = hv;
            hs[j] += hv; hq[j] = fmaf(hv, hv, hq[j]);
        }
    }
    #pragma unroll
    for (int j = 0; j < 4; j++){
        atomicAdd(&cs[tx*4+j], hs[j]);
        atomicAdd(&cq[tx*4+j], hq[j]);
    }
    __syncthreads();
    if (tid < 64){
        atomicAdd(&g_sum[oc0 + tid],   cs[tid]);
        atomicAdd(&g_sumsq[oc0 + tid], cq[tid]);
    }
}

// ---------------- K5d: out = x + w2 @ relu(bn(h)) + b2  (BN finalize fused) ----------------
__global__ __launch_bounds__(256) void k_out(const float* __restrict__ x,
                                             const float* __restrict__ w2,
                                             const float* __restrict__ b2,
                                             const float* __restrict__ gamma,
                                             const float* __restrict__ beta,
                                             float* __restrict__ out){
    __shared__ float As[32][65], Ws[32][65];
    __shared__ float ssc[C2], ssh[C2];
    int r0 = blockIdx.x*64, c0 = blockIdx.y*64;
    int b = r0 / NPT, n0 = r0 % NPT;
    int tid = threadIdx.x, tx = tid & 15, ty = tid >> 4;
    {
        int oc = tid;
        float inv = 1.f / (float)(BB*NPT);
        float mean = g_sum[oc] * inv;
        float var  = g_sumsq[oc] * inv - mean*mean;
        float rstd = rsqrtf(var + 1e-5f);
        float sc = rstd * gamma[oc];
        ssc[oc] = sc;
        ssh[oc] = beta[oc] - mean * sc;
    }
    __syncthreads();
    float acc[4][4] = {};
    for (int k0 = 0; k0 < C2; k0 += 32){
        #pragma unroll
        for (int it = 0; it < 8; it++){
            int kk = tid & 31, i = (tid >> 5) + it*8;
            float v = g_h[(size_t)(r0+i)*C2 + k0 + kk];
            As[kk][i] = fmaxf(fmaf(v, ssc[k0+kk], ssh[k0+kk]), 0.f);
        }
        #pragma unroll
        for (int it = 0; it < 8; it++){
            int kk = tid & 31, j = (tid >> 5) + it*8;
            Ws[kk][j] = w2[(c0+j)*C2 + k0 + kk];
        }
        __syncthreads();
        #pragma unroll
        for (int kk = 0; kk < 32; kk++){
            float a[4], w[4];
            #pragma unroll
            for (int u = 0; u < 4; u++){ a[u] = As[kk][ty*4+u]; w[u] = Ws[kk][tx*4+u]; }
            #pragma unroll
            for (int i = 0; i < 4; i++)
                #pragma unroll
                for (int j = 0; j < 4; j++)
                    acc[i][j] = fmaf(a[i], w[j], acc[i][j]);
        }
        __syncthreads();
    }
    #pragma unroll
    for (int i = 0; i < 4; i++){
        int n = n0 + ty*4 + i;
        #pragma unroll
        for (int j = 0; j < 4; j++){
            int c = c0 + tx*4 + j;
            size_t idx = (size_t)b*C*NPT + (size_t)c*NPT + n;
            out[idx] = x[idx] + b2[c] + acc[i][j];
        }
    }
}

// ---------------- launch ----------------
extern "C" void kernel_launch(void* const* d_in, const int* in_sizes, int n_in,
                              void* d_out, int out_size){
    const float* x     = (const float*)d_in[0];
    const float* wq    = (const float*)d_in[1];
    const float* bq    = (const float*)d_in[2];
    const float* wk    = (const float*)d_in[3];
    const float* bk    = (const float*)d_in[4];
    const float* wv    = (const float*)d_in[5];
    const float* bv    = (const float*)d_in[6];
    const float* wm    = (const float*)d_in[7];
    const float* bm    = (const float*)d_in[8];
    const float* w1    = (const float*)d_in[9];
    const float* b1    = (const float*)d_in[10];
    const float* gamma = (const float*)d_in[11];
    const float* beta  = (const float*)d_in[12];
    const float* w2    = (const float*)d_in[13];
    const float* b2    = (const float*)d_in[14];
    float* out = (float*)d_out;

    k_combine<<<C2, 128>>>(w1, b1, wm, bm);
    k_qkv<<<dim3(NPT/64, (3*C)/64, BB), 256>>>(x, wq, bq, wk, bk, wv, bv);
    k_gram<<<dim3(NTRI, 1, BB), 256>>>(x);
    k_topk<<<(BB*NPT)/8, 256>>>();
    k_attn<<<BB*NPT, 128>>>();
    k_hgemm<<<dim3((BB*NPT)/64, C2/64), 256>>>(x);
    k_out<<<dim3((BB*NPT)/64, C/64), 256>>>(x, w2, b2, gamma, beta, out);
}

// round 7
// speedup vs baseline: 1.5209x; 1.0505x over previous
#include <cuda_runtime.h>
#include <math.h>

#define BB   2
#define C    128
#define NPT  2048
#define H    4
#define D    32
#define KNN  20
#define C2   256

// ---------------- scratch (device globals; no runtime alloc) ----------------
__device__ float    g_q[BB*H*NPT*D];
__device__ float    g_k[BB*H*NPT*D];
__device__ float    g_v[BB*H*NPT*D];
__device__ float    g_gram[(size_t)BB*NPT*NPT];       // 33.5 MB (L2-resident)
__device__ int      g_idx[BB*NPT*KNN];
__device__ unsigned g_bits[BB*NPT*(NPT/32)];          // knn bitsets
__device__ float    g_av[(size_t)BB*NPT*C];           // (B,N,C)
__device__ float    g_Wh[C2*C2];                      // combined [w1x | w1a@wm]
__device__ float    g_bh[C2];
__device__ float    g_h[(size_t)BB*NPT*C2];           // pre-BN h, (B*N, 2C)
__device__ float    g_sum[C2], g_sumsq[C2];

#define NBW (BB*NPT*(NPT/32))                         // g_bits words
#define NT (NPT/128)                                  // 16 tiles
#define NTRI (NT*(NT+1)/2)                            // 136 tri-tiles per batch
#define GRAM_BLKS (NTRI*BB)                           // 272
#define QKV_BLKS  (32*6*BB)                           // 384
#define COMB_BLKS (C2/2)                              // 128
#define FUSEA_BLKS (GRAM_BLKS + QKV_BLKS + COMB_BLKS) // 784

// ================= fused kernel A: gram | qkv | combine =================
__global__ __launch_bounds__(256) void k_fusedA(
    const float* __restrict__ x,
    const float* __restrict__ wq, const float* __restrict__ bq,
    const float* __restrict__ wk, const float* __restrict__ bk,
    const float* __restrict__ wv, const float* __restrict__ bv,
    const float* __restrict__ w1, const float* __restrict__ b1,
    const float* __restrict__ wm, const float* __restrict__ bm)
{
    __shared__ float S[2*32*132 + 256];     // union scratch (~34.8KB)
    int bx = blockIdx.x;
    int tid = threadIdx.x;

    if (bx < GRAM_BLKS){
        // ---------------- gram (symmetric, upper-triangle tiles) ----------------
        float (*As)[132] = (float(*)[132])S;
        float (*Bs)[132] = (float(*)[132])(S + 32*132);
        float* xxm = S + 2*32*132;          // 128
        float* xxn = xxm + 128;             // 128
        int b = bx / NTRI;
        // zero a chunk of g_bits
        {
            int lo = bx*964, hi = bx*964 + 964; if (hi > NBW) hi = NBW;
            for (int w = lo + tid; w < hi; w += 256) g_bits[w] = 0u;
        }
        int u = bx % NTRI, ti = 0;
        while (u >= NT - ti){ u -= NT - ti; ti++; }
        int tj = ti + u;
        int n0 = ti*128, m0 = tj*128;
        int tx = tid & 15, ty = tid >> 4;
        const float* xb = x + (size_t)b*C*NPT;
        {
            int col = tid & 127;
            int base0 = (tid < 128) ? m0 : n0;
            float s = 0.f;
            #pragma unroll 4
            for (int c = 0; c < C; c++){ float v = xb[(size_t)c*NPT + base0 + col]; s = fmaf(v,v,s); }
            if (tid < 128) xxm[col] = s; else xxn[col] = s;
        }
        float acc[8][8] = {};
        for (int k0 = 0; k0 < C; k0 += 32){
            #pragma unroll
            for (int it = 0; it < 16; it++){
                int i = tid & 127, kk = (tid >> 7) + it*2;
                As[kk][i] = xb[(size_t)(k0+kk)*NPT + n0 + i];
                Bs[kk][i] = xb[(size_t)(k0+kk)*NPT + m0 + i];
            }
            __syncthreads();
            #pragma unroll
            for (int kk = 0; kk < 32; kk++){
                float4 a0 = *(const float4*)&As[kk][ty*8];
                float4 a1 = *(const float4*)&As[kk][ty*8+4];
                float4 b0 = *(const float4*)&Bs[kk][tx*8];
                float4 b1 = *(const float4*)&Bs[kk][tx*8+4];
                float a[8] = {a0.x,a0.y,a0.z,a0.w,a1.x,a1.y,a1.z,a1.w};
                float bb[8] = {b0.x,b0.y,b0.z,b0.w,b1.x,b1.y,b1.z,b1.w};
                #pragma unroll
                for (int i = 0; i < 8; i++)
                    #pragma unroll
                    for (int j = 0; j < 8; j++)
                        acc[i][j] = fmaf(a[i], bb[j], acc[i][j]);
            }
            __syncthreads();
        }
        float* gp = g_gram + (size_t)b*NPT*NPT;
        #pragma unroll
        for (int i = 0; i < 8; i++){
            int n = n0 + ty*8 + i;
            #pragma unroll
            for (int j = 0; j < 8; j++){
                int m = m0 + tx*8 + j;
                gp[(size_t)n*NPT + m] = 2.f*acc[i][j] - xxm[tx*8+j];
            }
        }
        if (ti != tj){
            float (*Ts)[36] = (float(*)[36])S;
            #pragma unroll
            for (int c = 0; c < 4; c++){
                __syncthreads();
                if ((ty >> 2) == c){
                    #pragma unroll
                    for (int i = 0; i < 8; i++){
                        int nl = ty*8 + i;
                        float xn = xxn[nl];
                        #pragma unroll
                        for (int j = 0; j < 8; j++)
                            Ts[tx*8 + j][nl - c*32] = 2.f*acc[i][j] - xn;
                    }
                }
                __syncthreads();
                int r = tid >> 1;
                int cl = (tid & 1)*16;
                #pragma unroll
                for (int q = 0; q < 4; q++){
                    float4 t4 = *(const float4*)&Ts[r][cl + q*4];
                    *(float4*)&gp[(size_t)(m0 + r)*NPT + n0 + c*32 + cl + q*4] = t4;
                }
            }
        }
    } else if (bx < GRAM_BLKS + QKV_BLKS){
        // ---------------- qkv ----------------
        float (*As)[65] = (float(*)[65])S;
        float (*Ws)[65] = (float(*)[65])(S + 32*65);
        int i0 = bx - GRAM_BLKS;
        int n0  = (i0 & 31)*64;
        int oc0 = ((i0 >> 5) % 6)*64;
        int b   = i0 / 192;
        int tx = tid & 15, ty = tid >> 4;
        float acc[4][4] = {};
        for (int k0 = 0; k0 < C; k0 += 32){
            #pragma unroll
            for (int it = 0; it < 8; it++){
                int i = tid & 63, kk = (tid >> 6) + it*4;
                As[kk][i] = x[(size_t)b*C*NPT + (size_t)(k0+kk)*NPT + n0 + i];
            }
            #pragma unroll
            for (int it = 0; it < 8; it++){
                int kk = tid & 31, j = (tid >> 5) + it*8;
                int oc = oc0 + j;
                const float* wp = (oc < C) ? wq : (oc < 2*C ? wk : wv);
                int ocl = oc & (C-1);
                Ws[kk][j] = wp[ocl*C + k0 + kk];
            }
            __syncthreads();
            #pragma unroll
            for (int kk = 0; kk < 32; kk++){
                float a[4], w[4];
                #pragma unroll
                for (int u = 0; u < 4; u++){ a[u] = As[kk][ty*4+u]; w[u] = Ws[kk][tx*4+u]; }
                #pragma unroll
                for (int i = 0; i < 4; i++)
                    #pragma unroll
                    for (int j = 0; j < 4; j++)
                        acc[i][j] = fmaf(a[i], w[j], acc[i][j]);
            }
            __syncthreads();
        }
        #pragma unroll
        for (int i = 0; i < 4; i++){
            int n = n0 + ty*4 + i;
            #pragma unroll
            for (int j = 0; j < 4; j++){
                int oc = oc0 + tx*4 + j;
                int t = oc >> 7, ocl = oc & (C-1);
                int h = ocl >> 5, d = ocl & 31;
                float bias = (t==0 ? bq : (t==1 ? bk : bv))[ocl];
                float* dst = (t==0 ? g_q : (t==1 ? g_k : g_v));
                dst[(((size_t)b*H + h)*NPT + n)*D + d] = acc[i][j] + bias;
            }
        }
    } else {
        // ---------------- combine: fold wm into w1, zero BN accumulators ----------------
        float* red = S;                                   // 256 floats
        int half = tid >> 7;
        int c = tid & 127;
        int oc = (bx - GRAM_BLKS - QKV_BLKS)*2 + half;
        if (c == 0){ g_sum[oc] = 0.f; g_sumsq[oc] = 0.f; }
        float s = 0.f;
        for (int c2 = 0; c2 < C; c2++)
            s = fmaf(w1[oc*C2 + C + c2], wm[c2*C + c], s);
        g_Wh[oc*C2 + C + c] = s;
        g_Wh[oc*C2 + c] = w1[oc*C2 + c];
        red[tid] = w1[oc*C2 + C + c] * bm[c];
        __syncthreads();
        for (int s2 = 64; s2; s2 >>= 1){
            if (c < s2) red[half*128 + c] += red[half*128 + c + s2];
            __syncthreads();
        }
        if (c == 0) g_bh[oc] = b1[oc] + red[half*128];
    }
}

// ---------------- K2b: top-K=20, radix select, ONE ROW PER WARP ----------------
__device__ __forceinline__ unsigned f2ord(float f){
    unsigned a = __float_as_uint(f);
    return a ^ ((a & 0x80000000u) ? 0xFFFFFFFFu : 0x80000000u);
}
__global__ __launch_bounds__(256) void k_topk(){
    int wid = threadIdx.x >> 5, lane = threadIdx.x & 31;
    int row = blockIdx.x*8 + wid;
    const float4* g4 = (const float4*)(g_gram + (size_t)row*NPT);
    __shared__ int      hist[8][256];
    __shared__ unsigned candV[8][128];
    __shared__ int      candI[8][128];
    __shared__ int      candCnt[8];
    __shared__ int      sT1[8], sK1[8], sT2[8];
    int* h = hist[wid];

    for (int i = lane; i < 256; i += 32) h[i] = 0;
    if (lane == 0) candCnt[wid] = 0;
    __syncwarp();

    // pass 1: byte-3 histogram (streaming)
    #pragma unroll 4
    for (int t = 0; t < 16; t++){
        float4 f = g4[t*32 + lane];
        atomicAdd(&h[f2ord(f.x) >> 24], 1);
        atomicAdd(&h[f2ord(f.y) >> 24], 1);
        atomicAdd(&h[f2ord(f.z) >> 24], 1);
        atomicAdd(&h[f2ord(f.w) >> 24], 1);
    }
    __syncwarp();
    {
        int c[8]; int base = lane*8; int gsum = 0;
        #pragma unroll
        for (int j = 0; j < 8; j++){ c[j] = h[base+j]; gsum += c[j]; }
        int acc = gsum;
        #pragma unroll
        for (int off = 1; off < 32; off <<= 1){
            int o = __shfl_down_sync(0xffffffffu, acc, off);
            if (lane + off < 32) acc += o;
        }
        int suf = acc - gsum;
        #pragma unroll
        for (int j = 7; j >= 0; j--){
            if (suf < KNN && suf + c[j] >= KNN){ sT1[wid] = base+j; sK1[wid] = KNN - suf; }
            suf += c[j];
        }
    }
    __syncwarp();
    unsigned T1 = (unsigned)sT1[wid]; int k1 = sK1[wid];

    // pass 2: byte-2 histogram within bin T1 (streaming)
    for (int i = lane; i < 256; i += 32) h[i] = 0;
    __syncwarp();
    #pragma unroll 4
    for (int t = 0; t < 16; t++){
        float4 f = g4[t*32 + lane];
        unsigned a;
        a = f2ord(f.x); if ((a >> 24) == T1) atomicAdd(&h[(a >> 16) & 255], 1);
        a = f2ord(f.y); if ((a >> 24) == T1) atomicAdd(&h[(a >> 16) & 255], 1);
        a = f2ord(f.z); if ((a >> 24) == T1) atomicAdd(&h[(a >> 16) & 255], 1);
        a = f2ord(f.w); if ((a >> 24) == T1) atomicAdd(&h[(a >> 16) & 255], 1);
    }
    __syncwarp();
    {
        int c[8]; int base = lane*8; int gsum = 0;
        #pragma unroll
        for (int j = 0; j < 8; j++){ c[j] = h[base+j]; gsum += c[j]; }
        int acc = gsum;
        #pragma unroll
        for (int off = 1; off < 32; off <<= 1){
            int o = __shfl_down_sync(0xffffffffu, acc, off);
            if (lane + off < 32) acc += o;
        }
        int suf = acc - gsum;
        #pragma unroll
        for (int j = 7; j >= 0; j--){
            if (suf < k1 && suf + c[j] >= k1){ sT2[wid] = base+j; }
            suf += c[j];
        }
    }
    __syncwarp();
    unsigned thr = (T1 << 8) | (unsigned)sT2[wid];

    // pass 3: collect candidates >= 16-bit threshold (superset of exact top-20)
    #pragma unroll 4
    for (int t = 0; t < 16; t++){
        float4 f = g4[t*32 + lane];
        int base = (t*32 + lane)*4;
        unsigned a;
        a = f2ord(f.x);
        if ((a >> 16) >= thr){ int p = atomicAdd(&candCnt[wid],1); if (p<128){ candV[wid][p]=a; candI[wid][p]=base+0; } }
        a = f2ord(f.y);
        if ((a >> 16) >= thr){ int p = atomicAdd(&candCnt[wid],1); if (p<128){ candV[wid][p]=a; candI[wid][p]=base+1; } }
        a = f2ord(f.z);
        if ((a >> 16) >= thr){ int p = atomicAdd(&candCnt[wid],1); if (p<128){ candV[wid][p]=a; candI[wid][p]=base+2; } }
        a = f2ord(f.w);
        if ((a >> 16) >= thr){ int p = atomicAdd(&candCnt[wid],1); if (p<128){ candV[wid][p]=a; candI[wid][p]=base+3; } }
    }
    __syncwarp();

    // exact top-20 among candidates (max value, min index — matches lax.top_k)
    int cc = min(candCnt[wid], 128);
    for (int r = 0; r < KNN; r++){
        unsigned bv = 0; int bi = 0x7fffffff;
        for (int i = lane; i < cc; i += 32){
            unsigned vv = candV[wid][i];
            if (vv > bv || (vv == bv && candI[wid][i] < bi)){ bv = vv; bi = candI[wid][i]; }
        }
        unsigned wm = __reduce_max_sync(0xffffffffu, bv);
        unsigned wiu = (bv == wm) ? (unsigned)bi : 0x7fffffffu;
        int wi = (int)__reduce_min_sync(0xffffffffu, wiu);
        for (int i = lane; i < cc; i += 32)
            if (candV[wid][i] == wm && candI[wid][i] == wi){ candV[wid][i] = 0u; candI[wid][i] = 0x7fffffff; }
        if (lane == 0){
            g_idx[row*KNN + r] = wi;
            atomicOr(&g_bits[(size_t)row*(NPT/32) + (wi >> 5)], 1u << (wi & 31));
        }
    }
}

// ---------------- K4: mutual-mask + sparse attention (warp = head) ----------------
// KNN loop fully unrolled (compile-time) so all gathers are in flight at once.
__global__ __launch_bounds__(128) void k_attn(){
    int row = blockIdx.x;              // b*NPT + n
    int b = row >> 11, n = row & (NPT-1);
    int tid = threadIdx.x;
    int h = tid >> 5, lane = tid & 31;
    __shared__ int adj[32]; __shared__ int scnt;
    __shared__ float sk[H][KNN][33];
    __shared__ float sv[H][KNN][33];
    __shared__ float sq[H][32];
    __shared__ float sp[H][32];
    if (tid < 32){
        adj[tid] = 0;                                   // pad: dummy row 0
        __syncwarp();
        int m = 0; bool ok = false;
        if (tid < KNN){
            m = g_idx[row*KNN + tid];
            ok = (g_bits[(size_t)(b*NPT + m)*(NPT/32) + (n >> 5)] >> (n & 31)) & 1u;
        }
        unsigned ball = __ballot_sync(0xffffffffu, ok);
        int pos = __popc(ball & ((1u << tid) - 1u));
        if (ok) adj[pos] = m;
        if (tid == 0) scnt = __popc(ball);
    }
    __syncthreads();
    int cnt = scnt;
    size_t hb = ((size_t)(b*H + h))*NPT*D;
    sq[h][lane] = g_q[hb + (size_t)n*D + lane];
    #pragma unroll
    for (int j = 0; j < KNN; j++){                      // fixed trip count: 40 loads in flight
        int m = adj[j];
        sk[h][j][lane] = g_k[hb + (size_t)m*D + lane];
        sv[h][j][lane] = g_v[hb + (size_t)m*D + lane];
    }
    __syncwarp();
    float s = -3.4e38f;
    if (lane < cnt){
        float a = 0.f;
        #pragma unroll 8
        for (int d = 0; d < 32; d++) a = fmaf(sq[h][d], sk[h][lane][d], a);
        s = a * 0.17677669529663687f;   // 1/sqrt(32)
    }
    float mx = s;
    #pragma unroll
    for (int off = 16; off; off >>= 1) mx = fmaxf(mx, __shfl_xor_sync(0xffffffffu, mx, off));
    float e = (lane < cnt) ? expf(s - mx) : 0.f;
    float se = e;
    #pragma unroll
    for (int off = 16; off; off >>= 1) se += __shfl_xor_sync(0xffffffffu, se, off);
    sp[h][lane] = e / se;               // 0 for lane >= cnt
    __syncwarp();
    float acc = 0.f;
    #pragma unroll
    for (int j = 0; j < KNN; j++)       // fixed trip count; sp=0 beyond cnt
        acc = fmaf(sp[h][j], sv[h][j][lane], acc);
    g_av[(size_t)row*C + h*D + lane] = acc;
}

// ---------------- K5b: h = Wh @ [x; av] + bh  (+ fused BN stats) ----------------
__global__ __launch_bounds__(256) void k_hgemm(const float* __restrict__ x){
    __shared__ float As[32][65], Ws[32][65];
    __shared__ float cs[64], cq[64];
    int r0 = blockIdx.x*64, oc0 = blockIdx.y*64;
    int b = r0 / NPT, n0 = r0 % NPT;
    int tid = threadIdx.x, tx = tid & 15, ty = tid >> 4;
    if (tid < 64){ cs[tid] = 0.f; cq[tid] = 0.f; }
    float acc[4][4] = {};
    for (int k0 = 0; k0 < C2; k0 += 32){
        if (k0 < C){
            #pragma unroll
            for (int it = 0; it < 8; it++){
                int i = tid & 63, kk = (tid >> 6) + it*4;
                As[kk][i] = x[(size_t)b*C*NPT + (size_t)(k0+kk)*NPT + n0 + i];
            }
        } else {
            #pragma unroll
            for (int it = 0; it < 8; it++){
                int kk = tid & 31, i = (tid >> 5) + it*8;
                As[kk][i] = g_av[(size_t)(r0+i)*C + (k0 - C + kk)];
            }
        }
        #pragma unroll
        for (int it = 0; it < 8; it++){
            int kk = tid & 31, j = (tid >> 5) + it*8;
            Ws[kk][j] = g_Wh[(oc0+j)*C2 + k0 + kk];
        }
        __syncthreads();
        #pragma unroll
        for (int kk = 0; kk < 32; kk++){
            float a[4], w[4];
            #pragma unroll
            for (int u = 0; u < 4; u++){ a[u] = As[kk][ty*4+u]; w[u] = Ws[kk][tx*4+u]; }
            #pragma unroll
            for (int i = 0; i < 4; i++)
                #pragma unroll
                for (int j = 0; j < 4; j++)
                    acc[i][j] = fmaf(a[i], w[j], acc[i][j]);
        }
        __syncthreads();
    }
    float hs[4] = {}, hq[4] = {};
    #pragma unroll
    for (int i = 0; i < 4; i++){
        int r = r0 + ty*4 + i;
        #pragma unroll
        for (int j = 0; j < 4; j++){
            int oc = oc0 + tx*4 + j;
            float hv = acc[i][j] + g_bh[oc];
            g_h[(size_t)r*C2 + oc] = hv;
            hs[j] += hv; hq[j] = fmaf(hv, hv, hq[j]);
        }
    }
    #pragma unroll
    for (int j = 0; j < 4; j++){
        atomicAdd(&cs[tx*4+j], hs[j]);
        atomicAdd(&cq[tx*4+j], hq[j]);
    }
    __syncthreads();
    if (tid < 64){
        atomicAdd(&g_sum[oc0 + tid],   cs[tid]);
        atomicAdd(&g_sumsq[oc0 + tid], cq[tid]);
    }
}

// ---------------- K5d: out = x + w2 @ relu(bn(h)) + b2  (BN finalize fused) ----------------
__global__ __launch_bounds__(256) void k_out(const float* __restrict__ x,
                                             const float* __restrict__ w2,
                                             const float* __restrict__ b2,
                                             const float* __restrict__ gamma,
                                             const float* __restrict__ beta,
                                             float* __restrict__ out){
    __shared__ float As[32][65], Ws[32][65];
    __shared__ float ssc[C2], ssh[C2];
    int r0 = blockIdx.x*64, c0 = blockIdx.y*64;
    int b = r0 / NPT, n0 = r0 % NPT;
    int tid = threadIdx.x, tx = tid & 15, ty = tid >> 4;
    {
        int oc = tid;
        float inv = 1.f / (float)(BB*NPT);
        float mean = g_sum[oc] * inv;
        float var  = g_sumsq[oc] * inv - mean*mean;
        float rstd = rsqrtf(var + 1e-5f);
        float sc = rstd * gamma[oc];
        ssc[oc] = sc;
        ssh[oc] = beta[oc] - mean * sc;
    }
    __syncthreads();
    float acc[4][4] = {};
    for (int k0 = 0; k0 < C2; k0 += 32){
        #pragma unroll
        for (int it = 0; it < 8; it++){
            int kk = tid & 31, i = (tid >> 5) + it*8;
            float v = g_h[(size_t)(r0+i)*C2 + k0 + kk];
            As[kk][i] = fmaxf(fmaf(v, ssc[k0+kk], ssh[k0+kk]), 0.f);
        }
        #pragma unroll
        for (int it = 0; it < 8; it++){
            int kk = tid & 31, j = (tid >> 5) + it*8;
            Ws[kk][j] = w2[(c0+j)*C2 + k0 + kk];
        }
        __syncthreads();
        #pragma unroll
        for (int kk = 0; kk < 32; kk++){
            float a[4], w[4];
            #pragma unroll
            for (int u = 0; u < 4; u++){ a[u] = As[kk][ty*4+u]; w[u] = Ws[kk][tx*4+u]; }
            #pragma unroll
            for (int i = 0; i < 4; i++)
                #pragma unroll
                for (int j = 0; j < 4; j++)
                    acc[i][j] = fmaf(a[i], w[j], acc[i][j]);
        }
        __syncthreads();
    }
    #pragma unroll
    for (int i = 0; i < 4; i++){
        int n = n0 + ty*4 + i;
        #pragma unroll
        for (int j = 0; j < 4; j++){
            int c = c0 + tx*4 + j;
            size_t idx = (size_t)b*C*NPT + (size_t)c*NPT + n;
            out[idx] = x[idx] + b2[c] + acc[i][j];
        }
    }
}

// ---------------- launch ----------------
extern "C" void kernel_launch(void* const* d_in, const int* in_sizes, int n_in,
                              void* d_out, int out_size){
    const float* x     = (const float*)d_in[0];
    const float* wq    = (const float*)d_in[1];
    const float* bq    = (const float*)d_in[2];
    const float* wk    = (const float*)d_in[3];
    const float* bk    = (const float*)d_in[4];
    const float* wv    = (const float*)d_in[5];
    const float* bv    = (const float*)d_in[6];
    const float* wm    = (const float*)d_in[7];
    const float* bm    = (const float*)d_in[8];
    const float* w1    = (const float*)d_in[9];
    const float* b1    = (const float*)d_in[10];
    const float* gamma = (const float*)d_in[11];
    const float* beta  = (const float*)d_in[12];
    const float* w2    = (const float*)d_in[13];
    const float* b2    = (const float*)d_in[14];
    float* out = (float*)d_out;

    k_fusedA<<<FUSEA_BLKS, 256>>>(x, wq, bq, wk, bk, wv, bv, w1, b1, wm, bm);
    k_topk<<<(BB*NPT)/8, 256>>>();
    k_attn<<<BB*NPT, 128>>>();
    k_hgemm<<<dim3((BB*NPT)/64, C2/64), 256>>>(x);
    k_out<<<dim3((BB*NPT)/64, C/64), 256>>>(x, w2, b2, gamma, beta, out);
}